// round 6
// baseline (speedup 1.0000x reference)
#include <cuda_runtime.h>
#include <cstdint>
#include <cstddef>

#define FEAT  128
#define NRELS 8
#define MAXN  100000

// Scratch: gated+transformed node features, layout [N][R][F] so each edge
// gathers one contiguous 512B row. 409.6 MB static device allocation
// (sanctioned scratch mechanism; no runtime allocation anywhere).
__device__ float g_hall[(size_t)MAXN * NRELS * FEAT];

// ---------------------------------------------------------------------------
// Phase 1: g_hall[n,r,:] = (h[n,:] @ W[r]) * sigmoid(h[n,:] @ gw[r])
// One block per (128-row node tile, relation). Full K=128 panel resident in
// shared memory; 8x8 register microtiles; all smem accesses conflict-free.
// ---------------------------------------------------------------------------
__global__ __launch_bounds__(256, 1)
void transform_kernel(const float* __restrict__ h,
                      const float* __restrict__ W,
                      const float* __restrict__ gw,
                      int N) {
    extern __shared__ float smem[];
    float* a_s = smem;                    // [k][i] transposed h tile (128x128)
    float* b_s = smem + FEAT * FEAT;      // [k][j] W_r (row-major = [k][f])
    float* g_s = smem + 2 * FEAT * FEAT;  // [128] sigmoid(gate) per local row

    const int r    = blockIdx.y;
    const int row0 = blockIdx.x * FEAT;
    const int t    = threadIdx.x;

    // Load W_r into smem (16384 floats = 4096 float4, 16 per thread).
    {
        const float4* Wv = (const float4*)(W + (size_t)r * FEAT * FEAT);
        float4* bv = (float4*)b_s;
#pragma unroll
        for (int i = 0; i < 16; i++) bv[i * 256 + t] = Wv[i * 256 + t];
    }

    // Load h tile transposed into a_s: a_s[k][i]. Thread t owns row rr=t&127,
    // half=t>>7 of the 32 float4 columns. Within a warp, lanes store to 32
    // distinct consecutive rows -> 32 distinct banks, conflict-free.
    {
        const int rr   = t & 127;
        const int half = t >> 7;
        const int gr   = row0 + rr;
        const bool valid = (gr < N);
        const float4* hv = (const float4*)(h + (size_t)gr * FEAT);
#pragma unroll
        for (int it = 0; it < 16; it++) {
            const int c4 = half * 16 + it;
            float4 v = valid ? hv[c4] : make_float4(0.f, 0.f, 0.f, 0.f);
            a_s[(c4 * 4 + 0) * FEAT + rr] = v.x;
            a_s[(c4 * 4 + 1) * FEAT + rr] = v.y;
            a_s[(c4 * 4 + 2) * FEAT + rr] = v.z;
            a_s[(c4 * 4 + 3) * FEAT + rr] = v.w;
        }
    }
    __syncthreads();

    // 16x16 thread grid; each thread owns rows {ty*4..+3, 64+ty*4..+3} and
    // cols {tx*4..+3, 64+tx*4..+3}. All smem reads are consecutive float4.
    const int tx = t & 15;
    const int ty = t >> 4;
    const int ia = ty * 4, ib = 64 + ty * 4;
    const int ja = tx * 4, jb = 64 + tx * 4;

    float acc[8][8];
#pragma unroll
    for (int ii = 0; ii < 8; ii++)
#pragma unroll
        for (int jj = 0; jj < 8; jj++) acc[ii][jj] = 0.f;

#pragma unroll 8
    for (int k = 0; k < FEAT; k++) {
        const float4 a0 = *(const float4*)(a_s + k * FEAT + ia);
        const float4 a1 = *(const float4*)(a_s + k * FEAT + ib);
        const float4 b0 = *(const float4*)(b_s + k * FEAT + ja);
        const float4 b1 = *(const float4*)(b_s + k * FEAT + jb);
        const float av[8] = {a0.x, a0.y, a0.z, a0.w, a1.x, a1.y, a1.z, a1.w};
        const float bw[8] = {b0.x, b0.y, b0.z, b0.w, b1.x, b1.y, b1.z, b1.w};
#pragma unroll
        for (int ii = 0; ii < 8; ii++)
#pragma unroll
            for (int jj = 0; jj < 8; jj++)
                acc[ii][jj] = fmaf(av[ii], bw[jj], acc[ii][jj]);
    }

    // Gate GEMV + sigmoid (threads 0..127; lanes hit distinct banks).
    if (t < FEAT) {
        const float* gwr = gw + r * FEAT;
        float g = 0.f;
#pragma unroll 8
        for (int k = 0; k < FEAT; k++)
            g = fmaf(a_s[k * FEAT + t], gwr[k], g);
        g_s[t] = 1.f / (1.f + expf(-g));
    }
    __syncthreads();

    // Scaled store: g_hall[n][r][f] = acc * sigmoid(gate[n,r])
#pragma unroll
    for (int ii = 0; ii < 8; ii++) {
        const int li = (ii < 4) ? (ia + ii) : (ib + (ii - 4));
        const int gi = row0 + li;
        if (gi < N) {
            const float s = g_s[li];
            float* dstp = g_hall + ((size_t)gi * NRELS + r) * FEAT;
            float4 o0, o1;
            o0.x = acc[ii][0] * s; o0.y = acc[ii][1] * s;
            o0.z = acc[ii][2] * s; o0.w = acc[ii][3] * s;
            o1.x = acc[ii][4] * s; o1.y = acc[ii][5] * s;
            o1.z = acc[ii][6] * s; o1.w = acc[ii][7] * s;
            *(float4*)(dstp + ja) = o0;
            *(float4*)(dstp + jb) = o1;
        }
    }
}

// ---------------------------------------------------------------------------
// Zero the output (replaces cudaMemsetAsync: kernel launches are the one
// capture path this harness demonstrably supports).
// ---------------------------------------------------------------------------
__global__ void zero_kernel(float4* __restrict__ out, int n4) {
    const int i = blockIdx.x * blockDim.x + threadIdx.x;
    if (i < n4) out[i] = make_float4(0.f, 0.f, 0.f, 0.f);
}

// ---------------------------------------------------------------------------
// Phase 2: per-edge gather + scaled vector-atomic scatter.
// One warp per edge: lane l handles features [4l, 4l+4).
// red.global.add.v4.f32 (sm_90+) quarters the atomic op count vs scalar.
// ---------------------------------------------------------------------------
__global__ __launch_bounds__(256)
void edge_kernel(const float* __restrict__ norm,
                 const int*   __restrict__ src,
                 const int*   __restrict__ dst,
                 const int*   __restrict__ rel,
                 float*       __restrict__ out,
                 int E) {
    const int e = blockIdx.x * 8 + (threadIdx.x >> 5);
    if (e >= E) return;
    const int lane = threadIdx.x & 31;

    const int   s  = __ldg(src + e);
    const int   d  = __ldg(dst + e);
    const int   rr = __ldg(rel + e);
    const float nm = __ldg(norm + e);

    const float4* p = (const float4*)(g_hall + ((size_t)s * NRELS + rr) * FEAT);
    const float4 v = p[lane];

    float* o = out + (size_t)d * FEAT + lane * 4;
    asm volatile("red.global.add.v4.f32 [%0], {%1, %2, %3, %4};"
                 :: "l"(o),
                    "f"(v.x * nm), "f"(v.y * nm), "f"(v.z * nm), "f"(v.w * nm)
                 : "memory");
}

// ---------------------------------------------------------------------------
// Phase 3: relu in place.
// ---------------------------------------------------------------------------
__global__ void relu_kernel(float* __restrict__ out, int n4) {
    const int i = blockIdx.x * blockDim.x + threadIdx.x;
    if (i < n4) {
        float4 v = ((float4*)out)[i];
        v.x = fmaxf(v.x, 0.f);
        v.y = fmaxf(v.y, 0.f);
        v.z = fmaxf(v.z, 0.f);
        v.w = fmaxf(v.w, 0.f);
        ((float4*)out)[i] = v;
    }
}

// ---------------------------------------------------------------------------
// Launch: transform -> zero(out) -> edge scatter -> relu.
// Kernel launches only on the default stream — graph-capturable, alloc-free.
// ---------------------------------------------------------------------------
extern "C" void kernel_launch(void* const* d_in, const int* in_sizes, int n_in,
                              void* d_out, int out_size) {
    const float* h    = (const float*)d_in[0];  // [N,128] f32
    const float* W    = (const float*)d_in[1];  // [8,128,128] f32
    const float* gw   = (const float*)d_in[2];  // [8,128,1] f32
    const float* norm = (const float*)d_in[3];  // [E,1] f32
    const int*   src  = (const int*)d_in[4];    // [E] i32
    const int*   dst  = (const int*)d_in[5];    // [E] i32
    const int*   rel  = (const int*)d_in[6];    // [E] i32
    float* out = (float*)d_out;                 // [N,128] f32

    const int N = in_sizes[0] / FEAT;
    const int E = in_sizes[4];

    const int smem_bytes = (2 * FEAT * FEAT + FEAT) * (int)sizeof(float);
    cudaFuncSetAttribute(transform_kernel,
                         cudaFuncAttributeMaxDynamicSharedMemorySize,
                         smem_bytes);

    dim3 tgrid((N + FEAT - 1) / FEAT, NRELS);
    transform_kernel<<<tgrid, 256, smem_bytes>>>(h, W, gw, N);

    const int n4 = out_size / 4;
    zero_kernel<<<(n4 + 255) / 256, 256>>>((float4*)out, n4);

    edge_kernel<<<(E + 7) / 8, 256>>>(norm, src, dst, rel, out, E);

    relu_kernel<<<(n4 + 255) / 256, 256>>>(out, n4);
}

// round 10
// speedup vs baseline: 1.6302x; 1.6302x over previous
#include <cuda_runtime.h>
#include <cuda_bf16.h>
#include <cstdint>
#include <cstddef>

#define FEAT  128
#define NRELS 8
#define MAXN  100000
#define KPAD  136           // padded k stride (elements): 272 B rows, conflict-free ldmatrix

// ---------------------------------------------------------------------------
// Global scratch (static __device__ arrays — sanctioned mechanism).
// g_B* are zero-initialized at module load, so pad columns read as 0.
// ---------------------------------------------------------------------------
__device__ float g_hall[(size_t)MAXN * NRELS * FEAT];            // [N][R][F] f32
__device__ unsigned short g_Bhi[NRELS * FEAT * KPAD];            // W^T hi, [r][n][k] padded
__device__ unsigned short g_Blo[NRELS * FEAT * KPAD];            // W^T lo

__device__ __forceinline__ uint32_t smem_to_u32(const void* p) {
    uint32_t a;
    asm("{ .reg .u64 t; cvta.to.shared.u64 t, %1; cvt.u32.u64 %0, t; }"
        : "=r"(a) : "l"(p));
    return a;
}

// ldmatrix x4: four 8x8 b16 tiles, per-lane row addresses (arch-agnostic, sm_75+)
#define LDSM_X4(r0, r1, r2, r3, addr)                                          \
    asm volatile("ldmatrix.sync.aligned.m8n8.x4.shared.b16 {%0,%1,%2,%3}, [%4];" \
                 : "=r"(r0), "=r"(r1), "=r"(r2), "=r"(r3) : "r"(addr))

// mma.sync m16n8k16 bf16 -> f32 accumulate (arch-agnostic, sm_80+)
__device__ __forceinline__ void mma_bf16(float* c, uint32_t a0, uint32_t a1,
                                         uint32_t a2, uint32_t a3,
                                         uint32_t b0, uint32_t b1) {
    asm volatile(
        "mma.sync.aligned.m16n8k16.row.col.f32.bf16.bf16.f32 "
        "{%0,%1,%2,%3}, {%4,%5,%6,%7}, {%8,%9}, {%0,%1,%2,%3};"
        : "+f"(c[0]), "+f"(c[1]), "+f"(c[2]), "+f"(c[3])
        : "r"(a0), "r"(a1), "r"(a2), "r"(a3), "r"(b0), "r"(b1));
}

__device__ __forceinline__ uint32_t bf2_bits(__nv_bfloat162 v) {
    return *reinterpret_cast<uint32_t*>(&v);
}

// ---------------------------------------------------------------------------
// Prep: W[r][k][f] -> W^T = B[n=f][k] hi/lo bf16, padded [r][128][KPAD].
// ---------------------------------------------------------------------------
__global__ void prep_w_kernel(const float* __restrict__ W) {
    const int idx = blockIdx.x * 256 + threadIdx.x;
    if (idx >= NRELS * FEAT * FEAT) return;
    const int r = idx >> 14;
    const int e = idx & 16383;
    const int n = e >> 7;        // output feature (B row)
    const int k = e & 127;       // contraction dim
    const float w = W[(size_t)r * FEAT * FEAT + k * FEAT + n];
    const __nv_bfloat16 hi = __float2bfloat16(w);
    const __nv_bfloat16 lo = __float2bfloat16(w - __bfloat162float(hi));
    const int o = (r * FEAT + n) * KPAD + k;
    g_Bhi[o] = *reinterpret_cast<const unsigned short*>(&hi);
    g_Blo[o] = *reinterpret_cast<const unsigned short*>(&lo);
}

// ---------------------------------------------------------------------------
// SMEM layout (bytes, all offsets 16B-aligned)
// ---------------------------------------------------------------------------
#define SM_GW     0                        // 8*128 f32      = 4096
#define SM_GATE   4096                     // 8*128 f32      = 4096
#define SM_H      8192                     // 128*129 f32    = 66048
#define SM_AHI    74240                    // 128*KPAD bf16  = 34816
#define SM_ALO    109056
#define SM_BHI    143872
#define SM_BLO    178688
#define SM_TOTAL  213504                   // 208.5 KB < 227 KB cap

// ---------------------------------------------------------------------------
// Transform: per 128-node tile, for all 8 relations:
//   g_hall[n,r,:] = (h_tile @ W_r) * sigmoid(h_tile @ gw_r)
// 3-term bf16-split via ldmatrix + mma.sync (HMMA), fp32 accumulate.
// ---------------------------------------------------------------------------
__global__ __launch_bounds__(256, 1)
void transform_mma_kernel(const float* __restrict__ h,
                          const float* __restrict__ gw,
                          int N) {
    extern __shared__ char smem[];
    const uint32_t sbase = smem_to_u32(smem);
    const int t     = threadIdx.x;
    const int wid   = t >> 5;
    const int lane  = t & 31;
    const int nrow0 = blockIdx.x * FEAT;

    // gate weights -> smem
    for (int i = t; i < NRELS * FEAT; i += 256)
        ((float*)(smem + SM_GW))[i] = gw[i];

    // A panels: load h tile, split to bf16 hi/lo (padded [m][KPAD]),
    // plus fp32 copy (stride 129) for the gate GEMV.
    {
        const int row  = t & 127;
        const int half = t >> 7;               // k in [half*64, half*64+64)
        const int gr   = nrow0 + row;
        const bool valid = (gr < N);
        const float4* src = (const float4*)(h + (size_t)gr * FEAT + half * 64);
        float* hrow = (float*)(smem + SM_H) + row * 129 + half * 64;
#pragma unroll
        for (int c = 0; c < 8; c++) {          // 8-element k chunks
            float4 v0 = valid ? src[c * 2 + 0] : make_float4(0.f, 0.f, 0.f, 0.f);
            float4 v1 = valid ? src[c * 2 + 1] : make_float4(0.f, 0.f, 0.f, 0.f);
            const float f[8] = {v0.x, v0.y, v0.z, v0.w, v1.x, v1.y, v1.z, v1.w};
#pragma unroll
            for (int i = 0; i < 8; i++) hrow[c * 8 + i] = f[i];

            uint32_t hp[4], lp[4];
#pragma unroll
            for (int i = 0; i < 4; i++) {
                __nv_bfloat162 hh = __floats2bfloat162_rn(f[2 * i], f[2 * i + 1]);
                hp[i] = bf2_bits(hh);
                const float r0 = f[2 * i]     - __bfloat162float(__low2bfloat16(hh));
                const float r1 = f[2 * i + 1] - __bfloat162float(__high2bfloat16(hh));
                lp[i] = bf2_bits(__floats2bfloat162_rn(r0, r1));
            }
            const int off = row * (KPAD * 2) + (half * 64 + c * 8) * 2;  // bytes
            *(uint4*)(smem + SM_AHI + off) = make_uint4(hp[0], hp[1], hp[2], hp[3]);
            *(uint4*)(smem + SM_ALO + off) = make_uint4(lp[0], lp[1], lp[2], lp[3]);
        }
    }
    __syncthreads();

    // Gates: sigmoid(h_row . gw_r). Stride-129 fp32 rows -> conflict-free.
#pragma unroll
    for (int p = 0; p < 4; p++) {
        const int r   = p * 2 + (t >> 7);
        const int row = t & 127;
        const float* hrow = (float*)(smem + SM_H) + row * 129;
        const float* gwr  = (float*)(smem + SM_GW) + r * FEAT;
        float g = 0.f;
#pragma unroll 8
        for (int k = 0; k < FEAT; k++) g = fmaf(hrow[k], gwr[k], g);
        ((float*)(smem + SM_GATE))[r * FEAT + row] = 1.f / (1.f + __expf(-g));
    }

    // Warp tiling: 4x2 warps; warp owns rows [Moff, Moff+32), cols [Noff, Noff+64)
    const int Moff = (wid & 3) * 32;
    const int Noff = (wid >> 2) * 64;
    const int q    = lane >> 3;     // ldmatrix matrix id
    const int lrow = lane & 7;      // ldmatrix row within matrix

    // Per-lane ldmatrix byte offsets (matrix order: (m0,k0),(m8,k0),(m0,k8),(m8,k8))
    const uint32_t a_off = (uint32_t)((Moff + (q & 1) * 8 + lrow) * (KPAD * 2)
                                      + (q >> 1) * 16);
    // B x4 over n-tile pair p: (n2p,k0),(n2p,k8),(n2p+1,k0),(n2p+1,k8)
    const uint32_t b_off = (uint32_t)((Noff + (q >> 1) * 8 + lrow) * (KPAD * 2)
                                      + (q & 1) * 16);

    for (int r = 0; r < NRELS; r++) {
        __syncthreads();   // previous iter's mma reads done before B overwrite
        // Copy B panels (hi+lo) into smem: 2*2176 uint4, 17 per thread.
        {
            const uint4* bh = (const uint4*)(g_Bhi + r * FEAT * KPAD);
            const uint4* bl = (const uint4*)(g_Blo + r * FEAT * KPAD);
            uint4* sh = (uint4*)(smem + SM_BHI);
            uint4* sl = (uint4*)(smem + SM_BLO);
            for (int i = t; i < FEAT * KPAD / 8; i += 256) {
                sh[i] = bh[i];
                sl[i] = bl[i];
            }
        }
        __syncthreads();

        float acc[2][8][4];
#pragma unroll
        for (int mt = 0; mt < 2; mt++)
#pragma unroll
            for (int nt = 0; nt < 8; nt++)
#pragma unroll
                for (int i = 0; i < 4; i++) acc[mt][nt][i] = 0.f;

#pragma unroll
        for (int ks = 0; ks < 8; ks++) {
            const uint32_t kb = (uint32_t)(ks * 32);   // k-step byte offset

            uint32_t ah[2][4], al[2][4];
#pragma unroll
            for (int mt = 0; mt < 2; mt++) {
                const uint32_t mb = (uint32_t)(mt * 16 * KPAD * 2);
                LDSM_X4(ah[mt][0], ah[mt][1], ah[mt][2], ah[mt][3],
                        sbase + SM_AHI + mb + kb + a_off);
                LDSM_X4(al[mt][0], al[mt][1], al[mt][2], al[mt][3],
                        sbase + SM_ALO + mb + kb + a_off);
            }
            uint32_t bh[16], bl[16];
#pragma unroll
            for (int p = 0; p < 4; p++) {
                const uint32_t nb = (uint32_t)(p * 16 * KPAD * 2);
                LDSM_X4(bh[p * 4 + 0], bh[p * 4 + 1], bh[p * 4 + 2], bh[p * 4 + 3],
                        sbase + SM_BHI + nb + kb + b_off);
                LDSM_X4(bl[p * 4 + 0], bl[p * 4 + 1], bl[p * 4 + 2], bl[p * 4 + 3],
                        sbase + SM_BLO + nb + kb + b_off);
            }
#pragma unroll
            for (int mt = 0; mt < 2; mt++)
#pragma unroll
                for (int nt = 0; nt < 8; nt++) {
                    const int bi = (nt >> 1) * 4 + (nt & 1) * 2;
                    // hi*hi + hi*lo + lo*hi, all into the same fp32 accum
                    mma_bf16(acc[mt][nt], ah[mt][0], ah[mt][1], ah[mt][2], ah[mt][3],
                             bh[bi], bh[bi + 1]);
                    mma_bf16(acc[mt][nt], ah[mt][0], ah[mt][1], ah[mt][2], ah[mt][3],
                             bl[bi], bl[bi + 1]);
                    mma_bf16(acc[mt][nt], al[mt][0], al[mt][1], al[mt][2], al[mt][3],
                             bh[bi], bh[bi + 1]);
                }
        }

        // Epilogue: scale by gate, store f32 to g_hall[n][r][:].
        const float* gate = (const float*)(smem + SM_GATE) + r * FEAT;
        const int g  = lane >> 2;
        const int tq = lane & 3;
#pragma unroll
        for (int mt = 0; mt < 2; mt++) {
            const int row0 = Moff + mt * 16 + g;
            const int row1 = row0 + 8;
            const int gi0 = nrow0 + row0;
            const int gi1 = nrow0 + row1;
            const float s0 = gate[row0];
            const float s1 = gate[row1];
            float* d0 = g_hall + ((size_t)gi0 * NRELS + r) * FEAT;
            float* d1 = g_hall + ((size_t)gi1 * NRELS + r) * FEAT;
#pragma unroll
            for (int nt = 0; nt < 8; nt++) {
                const int col = Noff + nt * 8 + tq * 2;
                if (gi0 < N)
                    *(float2*)(d0 + col) =
                        make_float2(acc[mt][nt][0] * s0, acc[mt][nt][1] * s0);
                if (gi1 < N)
                    *(float2*)(d1 + col) =
                        make_float2(acc[mt][nt][2] * s1, acc[mt][nt][3] * s1);
            }
        }
    }
}

// ---------------------------------------------------------------------------
// Zero output
// ---------------------------------------------------------------------------
__global__ void zero_kernel(float4* __restrict__ out, int n4) {
    const int i = blockIdx.x * blockDim.x + threadIdx.x;
    if (i < n4) out[i] = make_float4(0.f, 0.f, 0.f, 0.f);
}

// ---------------------------------------------------------------------------
// Edge scatter: warp per edge, red.global.add.v4.f32
// ---------------------------------------------------------------------------
__global__ __launch_bounds__(256)
void edge_kernel(const float* __restrict__ norm,
                 const int*   __restrict__ src,
                 const int*   __restrict__ dst,
                 const int*   __restrict__ rel,
                 float*       __restrict__ out,
                 int E) {
    const int e = blockIdx.x * 8 + (threadIdx.x >> 5);
    if (e >= E) return;
    const int lane = threadIdx.x & 31;

    const int   s  = __ldg(src + e);
    const int   d  = __ldg(dst + e);
    const int   rr = __ldg(rel + e);
    const float nm = __ldg(norm + e);

    const float4* p = (const float4*)(g_hall + ((size_t)s * NRELS + rr) * FEAT);
    const float4 v = p[lane];

    float* o = out + (size_t)d * FEAT + lane * 4;
    asm volatile("red.global.add.v4.f32 [%0], {%1, %2, %3, %4};"
                 :: "l"(o),
                    "f"(v.x * nm), "f"(v.y * nm), "f"(v.z * nm), "f"(v.w * nm)
                 : "memory");
}

// ---------------------------------------------------------------------------
// ReLU in place
// ---------------------------------------------------------------------------
__global__ void relu_kernel(float* __restrict__ out, int n4) {
    const int i = blockIdx.x * blockDim.x + threadIdx.x;
    if (i < n4) {
        float4 v = ((float4*)out)[i];
        v.x = fmaxf(v.x, 0.f);
        v.y = fmaxf(v.y, 0.f);
        v.z = fmaxf(v.z, 0.f);
        v.w = fmaxf(v.w, 0.f);
        ((float4*)out)[i] = v;
    }
}

// ---------------------------------------------------------------------------
// Launch: prep_w -> transform(HMMA) -> zero -> edge -> relu
// ---------------------------------------------------------------------------
extern "C" void kernel_launch(void* const* d_in, const int* in_sizes, int n_in,
                              void* d_out, int out_size) {
    const float* h    = (const float*)d_in[0];  // [N,128]
    const float* W    = (const float*)d_in[1];  // [8,128,128]
    const float* gw   = (const float*)d_in[2];  // [8,128,1]
    const float* norm = (const float*)d_in[3];  // [E,1]
    const int*   src  = (const int*)d_in[4];
    const int*   dst  = (const int*)d_in[5];
    const int*   rel  = (const int*)d_in[6];
    float* out = (float*)d_out;

    const int N = in_sizes[0] / FEAT;
    const int E = in_sizes[4];
    const int NT = (N + FEAT - 1) / FEAT;

    prep_w_kernel<<<(NRELS * FEAT * FEAT + 255) / 256, 256>>>(W);

    cudaFuncSetAttribute(transform_mma_kernel,
                         cudaFuncAttributeMaxDynamicSharedMemorySize, SM_TOTAL);
    transform_mma_kernel<<<NT, 256, SM_TOTAL>>>(h, gw, N);

    const int n4 = out_size / 4;
    zero_kernel<<<(n4 + 255) / 256, 256>>>((float4*)out, n4);

    edge_kernel<<<(E + 7) / 8, 256>>>(norm, src, dst, rel, out, E);

    relu_kernel<<<(n4 + 255) / 256, 256>>>(out, n4);
}

// round 13
// speedup vs baseline: 1.9285x; 1.1830x over previous
#include <cuda_runtime.h>
#include <cuda_bf16.h>
#include <cuda_fp16.h>
#include <cstdint>
#include <cstddef>

#define FEAT  128
#define NRELS 8
#define MAXN  100000
#define MAXE  600000
#define KPAD  136           // padded k stride (elements): 272 B rows, conflict-free ldmatrix
#define NBIN  100096        // 391 * 256 >= MAXN
#define NBLK  391
#define CH    16            // sorted edges per warp in segmented kernel

// ---------------------------------------------------------------------------
// Global scratch (static __device__ arrays — sanctioned mechanism)
// ---------------------------------------------------------------------------
__device__ __half g_hall[(size_t)MAXN * NRELS * FEAT];           // [N][R][F] fp16
__device__ unsigned short g_Bhi[NRELS * FEAT * KPAD];            // W^T hi bf16 padded
__device__ unsigned short g_Blo[NRELS * FEAT * KPAD];            // W^T lo
__device__ unsigned int   g_hist[NBIN];                          // hist -> excl prefix -> cursor
__device__ unsigned int   g_bsum[512];
__device__ unsigned int   g_boff[512];
__device__ uint4          g_rec[MAXE];                           // sorted {src|rel<<20, norm, dst, 0}

__device__ __forceinline__ uint32_t smem_to_u32(const void* p) {
    uint32_t a;
    asm("{ .reg .u64 t; cvta.to.shared.u64 t, %1; cvt.u32.u64 %0, t; }"
        : "=r"(a) : "l"(p));
    return a;
}

#define LDSM_X4(r0, r1, r2, r3, addr)                                          \
    asm volatile("ldmatrix.sync.aligned.m8n8.x4.shared.b16 {%0,%1,%2,%3}, [%4];" \
                 : "=r"(r0), "=r"(r1), "=r"(r2), "=r"(r3) : "r"(addr))

__device__ __forceinline__ void mma_bf16(float* c, uint32_t a0, uint32_t a1,
                                         uint32_t a2, uint32_t a3,
                                         uint32_t b0, uint32_t b1) {
    asm volatile(
        "mma.sync.aligned.m16n8k16.row.col.f32.bf16.bf16.f32 "
        "{%0,%1,%2,%3}, {%4,%5,%6,%7}, {%8,%9}, {%0,%1,%2,%3};"
        : "+f"(c[0]), "+f"(c[1]), "+f"(c[2]), "+f"(c[3])
        : "r"(a0), "r"(a1), "r"(a2), "r"(a3), "r"(b0), "r"(b1));
}

__device__ __forceinline__ uint32_t bf2_bits(__nv_bfloat162 v) {
    return *reinterpret_cast<uint32_t*>(&v);
}

// ---------------------------------------------------------------------------
// Prep: W[r][k][f] -> W^T = B[n=f][k] hi/lo bf16, padded [r][128][KPAD].
// ---------------------------------------------------------------------------
__global__ void prep_w_kernel(const float* __restrict__ W) {
    const int idx = blockIdx.x * 256 + threadIdx.x;
    if (idx >= NRELS * FEAT * FEAT) return;
    const int r = idx >> 14;
    const int e = idx & 16383;
    const int n = e >> 7;
    const int k = e & 127;
    const float w = W[(size_t)r * FEAT * FEAT + k * FEAT + n];
    const __nv_bfloat16 hi = __float2bfloat16(w);
    const __nv_bfloat16 lo = __float2bfloat16(w - __bfloat162float(hi));
    const int o = (r * FEAT + n) * KPAD + k;
    g_Bhi[o] = *reinterpret_cast<const unsigned short*>(&hi);
    g_Blo[o] = *reinterpret_cast<const unsigned short*>(&lo);
}

// ---------------------------------------------------------------------------
// SMEM layout (bytes)
// ---------------------------------------------------------------------------
#define SM_GW     0
#define SM_GATE   4096
#define SM_H      8192
#define SM_AHI    74240
#define SM_ALO    109056
#define SM_BHI    143872
#define SM_BLO    178688
#define SM_TOTAL  213504

// ---------------------------------------------------------------------------
// Transform: per 128-node tile, for all 8 relations:
//   g_hall[n,r,:] = fp16( (h_tile @ W_r) * sigmoid(h_tile @ gw_r) )
// 3-term bf16-split via ldmatrix + mma.sync (HMMA), fp32 accumulate.
// ---------------------------------------------------------------------------
__global__ __launch_bounds__(256, 1)
void transform_mma_kernel(const float* __restrict__ h,
                          const float* __restrict__ gw,
                          int N) {
    extern __shared__ char smem[];
    const uint32_t sbase = smem_to_u32(smem);
    const int t     = threadIdx.x;
    const int wid   = t >> 5;
    const int lane  = t & 31;
    const int nrow0 = blockIdx.x * FEAT;

    for (int i = t; i < NRELS * FEAT; i += 256)
        ((float*)(smem + SM_GW))[i] = gw[i];

    {
        const int row  = t & 127;
        const int half = t >> 7;
        const int gr   = nrow0 + row;
        const bool valid = (gr < N);
        const float4* src = (const float4*)(h + (size_t)gr * FEAT + half * 64);
        float* hrow = (float*)(smem + SM_H) + row * 129 + half * 64;
#pragma unroll
        for (int c = 0; c < 8; c++) {
            float4 v0 = valid ? src[c * 2 + 0] : make_float4(0.f, 0.f, 0.f, 0.f);
            float4 v1 = valid ? src[c * 2 + 1] : make_float4(0.f, 0.f, 0.f, 0.f);
            const float f[8] = {v0.x, v0.y, v0.z, v0.w, v1.x, v1.y, v1.z, v1.w};
#pragma unroll
            for (int i = 0; i < 8; i++) hrow[c * 8 + i] = f[i];

            uint32_t hp[4], lp[4];
#pragma unroll
            for (int i = 0; i < 4; i++) {
                __nv_bfloat162 hh = __floats2bfloat162_rn(f[2 * i], f[2 * i + 1]);
                hp[i] = bf2_bits(hh);
                const float r0 = f[2 * i]     - __bfloat162float(__low2bfloat16(hh));
                const float r1 = f[2 * i + 1] - __bfloat162float(__high2bfloat16(hh));
                lp[i] = bf2_bits(__floats2bfloat162_rn(r0, r1));
            }
            const int off = row * (KPAD * 2) + (half * 64 + c * 8) * 2;
            *(uint4*)(smem + SM_AHI + off) = make_uint4(hp[0], hp[1], hp[2], hp[3]);
            *(uint4*)(smem + SM_ALO + off) = make_uint4(lp[0], lp[1], lp[2], lp[3]);
        }
    }
    __syncthreads();

#pragma unroll
    for (int p = 0; p < 4; p++) {
        const int r   = p * 2 + (t >> 7);
        const int row = t & 127;
        const float* hrow = (float*)(smem + SM_H) + row * 129;
        const float* gwr  = (float*)(smem + SM_GW) + r * FEAT;
        float g = 0.f;
#pragma unroll 8
        for (int k = 0; k < FEAT; k++) g = fmaf(hrow[k], gwr[k], g);
        ((float*)(smem + SM_GATE))[r * FEAT + row] = 1.f / (1.f + __expf(-g));
    }

    const int Moff = (wid & 3) * 32;
    const int Noff = (wid >> 2) * 64;
    const int q    = lane >> 3;
    const int lrow = lane & 7;
    const uint32_t a_off = (uint32_t)((Moff + (q & 1) * 8 + lrow) * (KPAD * 2)
                                      + (q >> 1) * 16);
    const uint32_t b_off = (uint32_t)((Noff + (q >> 1) * 8 + lrow) * (KPAD * 2)
                                      + (q & 1) * 16);

    for (int r = 0; r < NRELS; r++) {
        __syncthreads();
        {
            const uint4* bh = (const uint4*)(g_Bhi + r * FEAT * KPAD);
            const uint4* bl = (const uint4*)(g_Blo + r * FEAT * KPAD);
            uint4* sh = (uint4*)(smem + SM_BHI);
            uint4* sl = (uint4*)(smem + SM_BLO);
            for (int i = t; i < FEAT * KPAD / 8; i += 256) {
                sh[i] = bh[i];
                sl[i] = bl[i];
            }
        }
        __syncthreads();

        float acc[2][8][4];
#pragma unroll
        for (int mt = 0; mt < 2; mt++)
#pragma unroll
            for (int nt = 0; nt < 8; nt++)
#pragma unroll
                for (int i = 0; i < 4; i++) acc[mt][nt][i] = 0.f;

#pragma unroll
        for (int ks = 0; ks < 8; ks++) {
            const uint32_t kb = (uint32_t)(ks * 32);
            uint32_t ah[2][4], al[2][4];
#pragma unroll
            for (int mt = 0; mt < 2; mt++) {
                const uint32_t mb = (uint32_t)(mt * 16 * KPAD * 2);
                LDSM_X4(ah[mt][0], ah[mt][1], ah[mt][2], ah[mt][3],
                        sbase + SM_AHI + mb + kb + a_off);
                LDSM_X4(al[mt][0], al[mt][1], al[mt][2], al[mt][3],
                        sbase + SM_ALO + mb + kb + a_off);
            }
            uint32_t bh[16], bl[16];
#pragma unroll
            for (int p = 0; p < 4; p++) {
                const uint32_t nb = (uint32_t)(p * 16 * KPAD * 2);
                LDSM_X4(bh[p * 4 + 0], bh[p * 4 + 1], bh[p * 4 + 2], bh[p * 4 + 3],
                        sbase + SM_BHI + nb + kb + b_off);
                LDSM_X4(bl[p * 4 + 0], bl[p * 4 + 1], bl[p * 4 + 2], bl[p * 4 + 3],
                        sbase + SM_BLO + nb + kb + b_off);
            }
#pragma unroll
            for (int mt = 0; mt < 2; mt++)
#pragma unroll
                for (int nt = 0; nt < 8; nt++) {
                    const int bi = (nt >> 1) * 4 + (nt & 1) * 2;
                    mma_bf16(acc[mt][nt], ah[mt][0], ah[mt][1], ah[mt][2], ah[mt][3],
                             bh[bi], bh[bi + 1]);
                    mma_bf16(acc[mt][nt], ah[mt][0], ah[mt][1], ah[mt][2], ah[mt][3],
                             bl[bi], bl[bi + 1]);
                    mma_bf16(acc[mt][nt], al[mt][0], al[mt][1], al[mt][2], al[mt][3],
                             bh[bi], bh[bi + 1]);
                }
        }

        // fp16 epilogue: scale by gate, store half2
        const float* gate = (const float*)(smem + SM_GATE) + r * FEAT;
        const int g  = lane >> 2;
        const int tq = lane & 3;
#pragma unroll
        for (int mt = 0; mt < 2; mt++) {
            const int row0 = Moff + mt * 16 + g;
            const int row1 = row0 + 8;
            const int gi0 = nrow0 + row0;
            const int gi1 = nrow0 + row1;
            const float s0 = gate[row0];
            const float s1 = gate[row1];
            __half* d0 = g_hall + ((size_t)gi0 * NRELS + r) * FEAT;
            __half* d1 = g_hall + ((size_t)gi1 * NRELS + r) * FEAT;
#pragma unroll
            for (int nt = 0; nt < 8; nt++) {
                const int col = Noff + nt * 8 + tq * 2;
                if (gi0 < N)
                    *(__half2*)(d0 + col) =
                        __floats2half2_rn(acc[mt][nt][0] * s0, acc[mt][nt][1] * s0);
                if (gi1 < N)
                    *(__half2*)(d1 + col) =
                        __floats2half2_rn(acc[mt][nt][2] * s1, acc[mt][nt][3] * s1);
            }
        }
    }
}

// ---------------------------------------------------------------------------
// Counting sort by dst
// ---------------------------------------------------------------------------
__global__ void zero_hist_kernel() {
    const int i = blockIdx.x * 256 + threadIdx.x;
    if (i < NBIN) g_hist[i] = 0u;
}

__global__ void hist_kernel(const int* __restrict__ dst, int E) {
    const int e = blockIdx.x * 256 + threadIdx.x;
    if (e < E) atomicAdd(&g_hist[dst[e]], 1u);
}

// In-place per-block exclusive scan of 256-bin chunks; block totals to g_bsum.
__global__ void scan_block_kernel() {
    __shared__ unsigned int s[256];
    const int t   = threadIdx.x;
    const int bin = blockIdx.x * 256 + t;
    const unsigned int v = g_hist[bin];
    s[t] = v;
    __syncthreads();
#pragma unroll
    for (int off = 1; off < 256; off <<= 1) {
        unsigned int y = (t >= off) ? s[t - off] : 0u;
        __syncthreads();
        s[t] += y;
        __syncthreads();
    }
    g_hist[bin] = s[t] - v;                 // exclusive within block
    if (t == 255) g_bsum[blockIdx.x] = s[255];
}

// Single-block exclusive scan of NBLK block sums.
__global__ void scan_tops_kernel() {
    __shared__ unsigned int s[512];
    const int t = threadIdx.x;
    const unsigned int v = (t < NBLK) ? g_bsum[t] : 0u;
    s[t] = v;
    __syncthreads();
#pragma unroll
    for (int off = 1; off < 512; off <<= 1) {
        unsigned int y = (t >= off) ? s[t - off] : 0u;
        __syncthreads();
        s[t] += y;
        __syncthreads();
    }
    if (t < NBLK) g_boff[t] = s[t] - v;
}

__global__ void scan_add_kernel() {
    const int bin = blockIdx.x * 256 + threadIdx.x;
    g_hist[bin] += g_boff[blockIdx.x];      // global exclusive prefix = cursor
}

__global__ void scatter_kernel(const float* __restrict__ norm,
                               const int*   __restrict__ src,
                               const int*   __restrict__ dst,
                               const int*   __restrict__ rel,
                               int E) {
    const int e = blockIdx.x * 256 + threadIdx.x;
    if (e >= E) return;
    const int d = dst[e];
    const unsigned int pos = atomicAdd(&g_hist[d], 1u);
    g_rec[pos] = make_uint4((unsigned)src[e] | ((unsigned)rel[e] << 20),
                            __float_as_uint(norm[e]), (unsigned)d, 0u);
}

// ---------------------------------------------------------------------------
// Segmented edge kernel: warp walks CH sorted edges, accumulates per-dst run
// in registers, one red.v4 per segment boundary.
// ---------------------------------------------------------------------------
__global__ __launch_bounds__(256)
void edge_seg_kernel(float* __restrict__ out, int E) {
    const int warp = blockIdx.x * 8 + (threadIdx.x >> 5);
    const int lane = threadIdx.x & 31;
    const int base = warp * CH;
    if (base >= E) return;
    const int end = (base + CH < E) ? base + CH : E;

    float4 acc = make_float4(0.f, 0.f, 0.f, 0.f);
    int cur = -1;

    for (int e = base; e < end; e++) {
        const uint4 rec = __ldg(&g_rec[e]);          // uniform -> broadcast
        const int d = (int)rec.z;
        if (d != cur) {
            if (cur >= 0) {
                float* o = out + (size_t)cur * FEAT + lane * 4;
                asm volatile("red.global.add.v4.f32 [%0], {%1, %2, %3, %4};"
                             :: "l"(o), "f"(acc.x), "f"(acc.y), "f"(acc.z), "f"(acc.w)
                             : "memory");
            }
            acc = make_float4(0.f, 0.f, 0.f, 0.f);
            cur = d;
        }
        const int s  = (int)(rec.x & 0xFFFFFu);
        const int rr = (int)(rec.x >> 20);
        const float nm = __uint_as_float(rec.y);

        const uint2 raw = __ldg((const uint2*)(g_hall +
                               ((size_t)s * NRELS + rr) * FEAT) + lane);
        const float2 f01 = __half22float2(*(const __half2*)&raw.x);
        const float2 f23 = __half22float2(*(const __half2*)&raw.y);
        acc.x = fmaf(f01.x, nm, acc.x);
        acc.y = fmaf(f01.y, nm, acc.y);
        acc.z = fmaf(f23.x, nm, acc.z);
        acc.w = fmaf(f23.y, nm, acc.w);
    }
    if (cur >= 0) {
        float* o = out + (size_t)cur * FEAT + lane * 4;
        asm volatile("red.global.add.v4.f32 [%0], {%1, %2, %3, %4};"
                     :: "l"(o), "f"(acc.x), "f"(acc.y), "f"(acc.z), "f"(acc.w)
                     : "memory");
    }
}

// ---------------------------------------------------------------------------
// Zero output / ReLU
// ---------------------------------------------------------------------------
__global__ void zero_kernel(float4* __restrict__ out, int n4) {
    const int i = blockIdx.x * blockDim.x + threadIdx.x;
    if (i < n4) out[i] = make_float4(0.f, 0.f, 0.f, 0.f);
}

__global__ void relu_kernel(float* __restrict__ out, int n4) {
    const int i = blockIdx.x * blockDim.x + threadIdx.x;
    if (i < n4) {
        float4 v = ((float4*)out)[i];
        v.x = fmaxf(v.x, 0.f);
        v.y = fmaxf(v.y, 0.f);
        v.z = fmaxf(v.z, 0.f);
        v.w = fmaxf(v.w, 0.f);
        ((float4*)out)[i] = v;
    }
}

// ---------------------------------------------------------------------------
// Launch
// ---------------------------------------------------------------------------
extern "C" void kernel_launch(void* const* d_in, const int* in_sizes, int n_in,
                              void* d_out, int out_size) {
    const float* h    = (const float*)d_in[0];
    const float* W    = (const float*)d_in[1];
    const float* gw   = (const float*)d_in[2];
    const float* norm = (const float*)d_in[3];
    const int*   src  = (const int*)d_in[4];
    const int*   dst  = (const int*)d_in[5];
    const int*   rel  = (const int*)d_in[6];
    float* out = (float*)d_out;

    const int N = in_sizes[0] / FEAT;
    const int E = in_sizes[4];
    const int NT = (N + FEAT - 1) / FEAT;
    const int EB = (E + 255) / 256;

    prep_w_kernel<<<(NRELS * FEAT * FEAT + 255) / 256, 256>>>(W);

    cudaFuncSetAttribute(transform_mma_kernel,
                         cudaFuncAttributeMaxDynamicSharedMemorySize, SM_TOTAL);
    transform_mma_kernel<<<NT, 256, SM_TOTAL>>>(h, gw, N);

    const int n4 = out_size / 4;
    zero_kernel<<<(n4 + 255) / 256, 256>>>((float4*)out, n4);

    // counting sort by dst
    zero_hist_kernel<<<NBLK, 256>>>();
    hist_kernel<<<EB, 256>>>(dst, E);
    scan_block_kernel<<<NBLK, 256>>>();
    scan_tops_kernel<<<1, 512>>>();
    scan_add_kernel<<<NBLK, 256>>>();
    scatter_kernel<<<EB, 256>>>(norm, src, dst, rel, E);

    // segmented scatter-add
    const int warps = (E + CH - 1) / CH;
    edge_seg_kernel<<<(warps + 7) / 8, 256>>>(out, E);

    relu_kernel<<<(n4 + 255) / 256, 256>>>(out, n4);
}

// round 14
// speedup vs baseline: 2.1115x; 1.0949x over previous
#include <cuda_runtime.h>
#include <cuda_bf16.h>
#include <cuda_fp16.h>
#include <cstdint>
#include <cstddef>

#define FEAT  128
#define NRELS 8
#define MAXN  100000
#define MAXE  600000
#define KPAD  136           // padded k stride (elements): 272 B rows, conflict-free ldmatrix
#define NBINP 100096        // 391 * 256 >= MAXN (pair bins per rel, and dst bins)
#define NBLK  391
#define CH    16            // sorted edges per warp in segmented kernel
#define MAXPAIR (NRELS * NBINP)   // 800768: upper bound on padded compact pairs

// ---------------------------------------------------------------------------
// Global scratch (static __device__ arrays — sanctioned mechanism)
// ---------------------------------------------------------------------------
__device__ __half g_hall[(size_t)MAXPAIR * FEAT];                // [cid][F] fp16
__device__ unsigned short g_Bhi[NRELS * FEAT * KPAD];            // W^T hi bf16 padded
__device__ unsigned short g_Blo[NRELS * FEAT * KPAD];            // W^T lo
// pair compaction
__device__ unsigned int g_pflag[NRELS * NBINP];                  // usage count per (rel,src)
__device__ unsigned int g_pidx[NRELS * NBINP];                   // scan -> global compact id
__device__ unsigned int g_bsum2[NRELS * 512];
__device__ unsigned int g_boff2[NRELS * 512];
__device__ unsigned int g_ptot[NRELS];
__device__ unsigned int g_pbase[NRELS + 1];                      // padded rel bases; [8]=M
__device__ unsigned int g_pairsrc[MAXPAIR];                      // src per compact slot
// dst sort
__device__ unsigned int g_hist[NBINP];
__device__ unsigned int g_bsum[512];
__device__ unsigned int g_boff[512];
__device__ uint4        g_rec[MAXE];                             // sorted {cid, norm, dst, 0}

__device__ __forceinline__ uint32_t smem_to_u32(const void* p) {
    uint32_t a;
    asm("{ .reg .u64 t; cvta.to.shared.u64 t, %1; cvt.u32.u64 %0, t; }"
        : "=r"(a) : "l"(p));
    return a;
}

#define LDSM_X4(r0, r1, r2, r3, addr)                                          \
    asm volatile("ldmatrix.sync.aligned.m8n8.x4.shared.b16 {%0,%1,%2,%3}, [%4];" \
                 : "=r"(r0), "=r"(r1), "=r"(r2), "=r"(r3) : "r"(addr))

__device__ __forceinline__ void mma_bf16(float* c, uint32_t a0, uint32_t a1,
                                         uint32_t a2, uint32_t a3,
                                         uint32_t b0, uint32_t b1) {
    asm volatile(
        "mma.sync.aligned.m16n8k16.row.col.f32.bf16.bf16.f32 "
        "{%0,%1,%2,%3}, {%4,%5,%6,%7}, {%8,%9}, {%0,%1,%2,%3};"
        : "+f"(c[0]), "+f"(c[1]), "+f"(c[2]), "+f"(c[3])
        : "r"(a0), "r"(a1), "r"(a2), "r"(a3), "r"(b0), "r"(b1));
}

__device__ __forceinline__ uint32_t bf2_bits(__nv_bfloat162 v) {
    return *reinterpret_cast<uint32_t*>(&v);
}

// ---------------------------------------------------------------------------
// Prep: W[r][k][f] -> W^T = B[n=f][k] hi/lo bf16, padded [r][128][KPAD].
// ---------------------------------------------------------------------------
__global__ void prep_w_kernel(const float* __restrict__ W) {
    const int idx = blockIdx.x * 256 + threadIdx.x;
    if (idx >= NRELS * FEAT * FEAT) return;
    const int r = idx >> 14;
    const int e = idx & 16383;
    const int n = e >> 7;
    const int k = e & 127;
    const float w = W[(size_t)r * FEAT * FEAT + k * FEAT + n];
    const __nv_bfloat16 hi = __float2bfloat16(w);
    const __nv_bfloat16 lo = __float2bfloat16(w - __bfloat162float(hi));
    const int o = (r * FEAT + n) * KPAD + k;
    g_Bhi[o] = *reinterpret_cast<const unsigned short*>(&hi);
    g_Blo[o] = *reinterpret_cast<const unsigned short*>(&lo);
}

// ---------------------------------------------------------------------------
// Pair compaction pipeline
// ---------------------------------------------------------------------------
__global__ void pair_init_kernel() {
    const int i = blockIdx.x * 256 + threadIdx.x;
    if (i < NRELS * NBINP) g_pflag[i] = 0u;
    if (i < MAXPAIR)       g_pairsrc[i] = 0u;
}

__global__ void pair_hist_kernel(const int* __restrict__ src,
                                 const int* __restrict__ rel, int E) {
    const int e = blockIdx.x * 256 + threadIdx.x;
    if (e < E) atomicAdd(&g_pflag[rel[e] * NBINP + src[e]], 1u);
}

__global__ void pscan_block_kernel() {
    __shared__ unsigned int s[256];
    const int rel = blockIdx.y;
    const int t   = threadIdx.x;
    const int bin = rel * NBINP + blockIdx.x * 256 + t;
    const unsigned int v = g_pflag[bin] ? 1u : 0u;
    s[t] = v;
    __syncthreads();
#pragma unroll
    for (int off = 1; off < 256; off <<= 1) {
        unsigned int y = (t >= off) ? s[t - off] : 0u;
        __syncthreads();
        s[t] += y;
        __syncthreads();
    }
    g_pidx[bin] = s[t] - v;                       // exclusive within block
    if (t == 255) g_bsum2[rel * 512 + blockIdx.x] = s[255];
}

__global__ void pscan_tops_kernel() {
    __shared__ unsigned int s[512];
    const int rel = blockIdx.x;
    const int t   = threadIdx.x;
    const unsigned int v = (t < NBLK) ? g_bsum2[rel * 512 + t] : 0u;
    s[t] = v;
    __syncthreads();
#pragma unroll
    for (int off = 1; off < 512; off <<= 1) {
        unsigned int y = (t >= off) ? s[t - off] : 0u;
        __syncthreads();
        s[t] += y;
        __syncthreads();
    }
    if (t < NBLK) g_boff2[rel * 512 + t] = s[t] - v;
    if (t == NBLK - 1) g_ptot[rel] = s[t];        // rel total (inclusive last)
}

__global__ void pad_base_kernel() {
    unsigned int base = 0;
    for (int r = 0; r < NRELS; r++) {
        g_pbase[r] = base;
        base += ((g_ptot[r] + 127u) / 128u) * 128u;   // pad to 128 -> pure tiles
    }
    g_pbase[NRELS] = base;
}

__global__ void pscan_add_kernel() {
    const int rel = blockIdx.y;
    const int bin = rel * NBINP + blockIdx.x * 256 + threadIdx.x;
    g_pidx[bin] += g_boff2[rel * 512 + blockIdx.x];   // rel-local exclusive
}

__global__ void build_pairs_kernel() {
    const int rel = blockIdx.y;
    const int sidx = blockIdx.x * 256 + threadIdx.x;  // src candidate
    const int bin  = rel * NBINP + sidx;
    if (g_pflag[bin]) {
        const unsigned int cid = g_pbase[rel] + g_pidx[bin];
        g_pairsrc[cid] = (unsigned int)sidx;
        g_pidx[bin]    = cid;                         // final: global compact id
    }
}

// ---------------------------------------------------------------------------
// SMEM layout (bytes)
// ---------------------------------------------------------------------------
#define SM_GW     0                        // 128 f32 = 512
#define SM_GATE   512                      // 128 f32 = 512
#define SM_H      1024                     // 128*129 f32 = 66048
#define SM_AHI    67072                    // 128*KPAD bf16 = 34816
#define SM_ALO    101888
#define SM_BHI    136704
#define SM_BLO    171520
#define SM_TOTAL  206336                   // 201.5 KB

// ---------------------------------------------------------------------------
// Transform: one block per compact 128-pair tile (single relation each):
//   g_hall[cid,:] = fp16( (h[src] @ W_rel) * sigmoid(h[src] . gw_rel) )
// 3-term bf16-split via ldmatrix + mma.sync, fp32 accumulate.
// Launched at worst-case grid; early-exits past the actual tile count.
// ---------------------------------------------------------------------------
__global__ __launch_bounds__(256, 1)
void transform_mma_kernel(const float* __restrict__ h,
                          const float* __restrict__ gw) {
    const int tile  = blockIdx.x;
    const int tbase = tile * 128;
    if ((unsigned)tbase >= g_pbase[NRELS]) return;   // uniform early exit

    int rel = 0;
#pragma unroll
    for (int r = 1; r < NRELS; r++)
        if ((unsigned)tbase >= g_pbase[r]) rel = r;

    extern __shared__ char smem[];
    const uint32_t sbase = smem_to_u32(smem);
    const int t    = threadIdx.x;
    const int wid  = t >> 5;
    const int lane = t & 31;

    if (t < FEAT) ((float*)(smem + SM_GW))[t] = gw[rel * FEAT + t];

    // B panel (hi+lo) once per block
    {
        const uint4* bh = (const uint4*)(g_Bhi + rel * FEAT * KPAD);
        const uint4* bl = (const uint4*)(g_Blo + rel * FEAT * KPAD);
        uint4* sh = (uint4*)(smem + SM_BHI);
        uint4* sl = (uint4*)(smem + SM_BLO);
        for (int i = t; i < FEAT * KPAD / 8; i += 256) {
            sh[i] = bh[i];
            sl[i] = bl[i];
        }
    }

    // A panel: gather rows by pairsrc, split to bf16 hi/lo + fp32 copy.
    {
        const int row  = t & 127;
        const int half = t >> 7;
        const int gsrc = (int)g_pairsrc[tbase + row];
        const float4* src = (const float4*)(h + (size_t)gsrc * FEAT + half * 64);
        float* hrow = (float*)(smem + SM_H) + row * 129 + half * 64;
#pragma unroll
        for (int c = 0; c < 8; c++) {
            const float4 v0 = __ldg(src + c * 2 + 0);
            const float4 v1 = __ldg(src + c * 2 + 1);
            const float f[8] = {v0.x, v0.y, v0.z, v0.w, v1.x, v1.y, v1.z, v1.w};
#pragma unroll
            for (int i = 0; i < 8; i++) hrow[c * 8 + i] = f[i];

            uint32_t hp[4], lp[4];
#pragma unroll
            for (int i = 0; i < 4; i++) {
                __nv_bfloat162 hh = __floats2bfloat162_rn(f[2 * i], f[2 * i + 1]);
                hp[i] = bf2_bits(hh);
                const float r0 = f[2 * i]     - __bfloat162float(__low2bfloat16(hh));
                const float r1 = f[2 * i + 1] - __bfloat162float(__high2bfloat16(hh));
                lp[i] = bf2_bits(__floats2bfloat162_rn(r0, r1));
            }
            const int off = row * (KPAD * 2) + (half * 64 + c * 8) * 2;
            *(uint4*)(smem + SM_AHI + off) = make_uint4(hp[0], hp[1], hp[2], hp[3]);
            *(uint4*)(smem + SM_ALO + off) = make_uint4(lp[0], lp[1], lp[2], lp[3]);
        }
    }
    __syncthreads();

    // Gates: one per row (single rel per tile)
    if (t < FEAT) {
        const float* hrow = (float*)(smem + SM_H) + t * 129;
        const float* gwr  = (float*)(smem + SM_GW);
        float g = 0.f;
#pragma unroll 8
        for (int k = 0; k < FEAT; k++) g = fmaf(hrow[k], gwr[k], g);
        ((float*)(smem + SM_GATE))[t] = 1.f / (1.f + __expf(-g));
    }
    __syncthreads();

    const int Moff = (wid & 3) * 32;
    const int Noff = (wid >> 2) * 64;
    const int q    = lane >> 3;
    const int lrow = lane & 7;
    const uint32_t a_off = (uint32_t)((Moff + (q & 1) * 8 + lrow) * (KPAD * 2)
                                      + (q >> 1) * 16);
    const uint32_t b_off = (uint32_t)((Noff + (q >> 1) * 8 + lrow) * (KPAD * 2)
                                      + (q & 1) * 16);

    float acc[2][8][4];
#pragma unroll
    for (int mt = 0; mt < 2; mt++)
#pragma unroll
        for (int nt = 0; nt < 8; nt++)
#pragma unroll
            for (int i = 0; i < 4; i++) acc[mt][nt][i] = 0.f;

#pragma unroll
    for (int ks = 0; ks < 8; ks++) {
        const uint32_t kb = (uint32_t)(ks * 32);
        uint32_t ah[2][4], al[2][4];
#pragma unroll
        for (int mt = 0; mt < 2; mt++) {
            const uint32_t mb = (uint32_t)(mt * 16 * KPAD * 2);
            LDSM_X4(ah[mt][0], ah[mt][1], ah[mt][2], ah[mt][3],
                    sbase + SM_AHI + mb + kb + a_off);
            LDSM_X4(al[mt][0], al[mt][1], al[mt][2], al[mt][3],
                    sbase + SM_ALO + mb + kb + a_off);
        }
        uint32_t bh[16], bl[16];
#pragma unroll
        for (int p = 0; p < 4; p++) {
            const uint32_t nb = (uint32_t)(p * 16 * KPAD * 2);
            LDSM_X4(bh[p * 4 + 0], bh[p * 4 + 1], bh[p * 4 + 2], bh[p * 4 + 3],
                    sbase + SM_BHI + nb + kb + b_off);
            LDSM_X4(bl[p * 4 + 0], bl[p * 4 + 1], bl[p * 4 + 2], bl[p * 4 + 3],
                    sbase + SM_BLO + nb + kb + b_off);
        }
#pragma unroll
        for (int mt = 0; mt < 2; mt++)
#pragma unroll
            for (int nt = 0; nt < 8; nt++) {
                const int bi = (nt >> 1) * 4 + (nt & 1) * 2;
                mma_bf16(acc[mt][nt], ah[mt][0], ah[mt][1], ah[mt][2], ah[mt][3],
                         bh[bi], bh[bi + 1]);
                mma_bf16(acc[mt][nt], ah[mt][0], ah[mt][1], ah[mt][2], ah[mt][3],
                         bl[bi], bl[bi + 1]);
                mma_bf16(acc[mt][nt], al[mt][0], al[mt][1], al[mt][2], al[mt][3],
                         bh[bi], bh[bi + 1]);
            }
    }

    // fp16 epilogue: scale by gate, store half2 to g_hall[cid]
    const float* gate = (const float*)(smem + SM_GATE);
    const int g  = lane >> 2;
    const int tq = lane & 3;
#pragma unroll
    for (int mt = 0; mt < 2; mt++) {
        const int row0 = Moff + mt * 16 + g;
        const int row1 = row0 + 8;
        const float s0 = gate[row0];
        const float s1 = gate[row1];
        __half* d0 = g_hall + (size_t)(tbase + row0) * FEAT;
        __half* d1 = g_hall + (size_t)(tbase + row1) * FEAT;
#pragma unroll
        for (int nt = 0; nt < 8; nt++) {
            const int col = Noff + nt * 8 + tq * 2;
            *(__half2*)(d0 + col) =
                __floats2half2_rn(acc[mt][nt][0] * s0, acc[mt][nt][1] * s0);
            *(__half2*)(d1 + col) =
                __floats2half2_rn(acc[mt][nt][2] * s1, acc[mt][nt][3] * s1);
        }
    }
}

// ---------------------------------------------------------------------------
// Counting sort by dst (unchanged machinery)
// ---------------------------------------------------------------------------
__global__ void zero_hist_kernel() {
    const int i = blockIdx.x * 256 + threadIdx.x;
    if (i < NBINP) g_hist[i] = 0u;
}

__global__ void hist_kernel(const int* __restrict__ dst, int E) {
    const int e = blockIdx.x * 256 + threadIdx.x;
    if (e < E) atomicAdd(&g_hist[dst[e]], 1u);
}

__global__ void scan_block_kernel() {
    __shared__ unsigned int s[256];
    const int t   = threadIdx.x;
    const int bin = blockIdx.x * 256 + t;
    const unsigned int v = g_hist[bin];
    s[t] = v;
    __syncthreads();
#pragma unroll
    for (int off = 1; off < 256; off <<= 1) {
        unsigned int y = (t >= off) ? s[t - off] : 0u;
        __syncthreads();
        s[t] += y;
        __syncthreads();
    }
    g_hist[bin] = s[t] - v;
    if (t == 255) g_bsum[blockIdx.x] = s[255];
}

__global__ void scan_tops_kernel() {
    __shared__ unsigned int s[512];
    const int t = threadIdx.x;
    const unsigned int v = (t < NBLK) ? g_bsum[t] : 0u;
    s[t] = v;
    __syncthreads();
#pragma unroll
    for (int off = 1; off < 512; off <<= 1) {
        unsigned int y = (t >= off) ? s[t - off] : 0u;
        __syncthreads();
        s[t] += y;
        __syncthreads();
    }
    if (t < NBLK) g_boff[t] = s[t] - v;
}

__global__ void scan_add_kernel() {
    const int bin = blockIdx.x * 256 + threadIdx.x;
    g_hist[bin] += g_boff[blockIdx.x];
}

__global__ void scatter_kernel(const float* __restrict__ norm,
                               const int*   __restrict__ src,
                               const int*   __restrict__ dst,
                               const int*   __restrict__ rel,
                               int E) {
    const int e = blockIdx.x * 256 + threadIdx.x;
    if (e >= E) return;
    const int d = dst[e];
    const unsigned int pos = atomicAdd(&g_hist[d], 1u);
    const unsigned int cid = g_pidx[rel[e] * NBINP + src[e]];
    g_rec[pos] = make_uint4(cid, __float_as_uint(norm[e]), (unsigned)d, 0u);
}

// ---------------------------------------------------------------------------
// Segmented edge kernel: warp walks CH sorted edges, one red.v4 per dst run.
// ---------------------------------------------------------------------------
__global__ __launch_bounds__(256)
void edge_seg_kernel(float* __restrict__ out, int E) {
    const int warp = blockIdx.x * 8 + (threadIdx.x >> 5);
    const int lane = threadIdx.x & 31;
    const int base = warp * CH;
    if (base >= E) return;
    const int end = (base + CH < E) ? base + CH : E;

    float4 acc = make_float4(0.f, 0.f, 0.f, 0.f);
    int cur = -1;

    for (int e = base; e < end; e++) {
        const uint4 rec = __ldg(&g_rec[e]);
        const int d = (int)rec.z;
        if (d != cur) {
            if (cur >= 0) {
                float* o = out + (size_t)cur * FEAT + lane * 4;
                asm volatile("red.global.add.v4.f32 [%0], {%1, %2, %3, %4};"
                             :: "l"(o), "f"(acc.x), "f"(acc.y), "f"(acc.z), "f"(acc.w)
                             : "memory");
            }
            acc = make_float4(0.f, 0.f, 0.f, 0.f);
            cur = d;
        }
        const float nm = __uint_as_float(rec.y);
        const uint2 raw = __ldg((const uint2*)(g_hall + (size_t)rec.x * FEAT) + lane);
        const float2 f01 = __half22float2(*(const __half2*)&raw.x);
        const float2 f23 = __half22float2(*(const __half2*)&raw.y);
        acc.x = fmaf(f01.x, nm, acc.x);
        acc.y = fmaf(f01.y, nm, acc.y);
        acc.z = fmaf(f23.x, nm, acc.z);
        acc.w = fmaf(f23.y, nm, acc.w);
    }
    if (cur >= 0) {
        float* o = out + (size_t)cur * FEAT + lane * 4;
        asm volatile("red.global.add.v4.f32 [%0], {%1, %2, %3, %4};"
                     :: "l"(o), "f"(acc.x), "f"(acc.y), "f"(acc.z), "f"(acc.w)
                     : "memory");
    }
}

// ---------------------------------------------------------------------------
// Zero output / ReLU
// ---------------------------------------------------------------------------
__global__ void zero_kernel(float4* __restrict__ out, int n4) {
    const int i = blockIdx.x * blockDim.x + threadIdx.x;
    if (i < n4) out[i] = make_float4(0.f, 0.f, 0.f, 0.f);
}

__global__ void relu_kernel(float* __restrict__ out, int n4) {
    const int i = blockIdx.x * blockDim.x + threadIdx.x;
    if (i < n4) {
        float4 v = ((float4*)out)[i];
        v.x = fmaxf(v.x, 0.f);
        v.y = fmaxf(v.y, 0.f);
        v.z = fmaxf(v.z, 0.f);
        v.w = fmaxf(v.w, 0.f);
        ((float4*)out)[i] = v;
    }
}

// ---------------------------------------------------------------------------
// Launch
// ---------------------------------------------------------------------------
extern "C" void kernel_launch(void* const* d_in, const int* in_sizes, int n_in,
                              void* d_out, int out_size) {
    const float* h    = (const float*)d_in[0];
    const float* W    = (const float*)d_in[1];
    const float* gw   = (const float*)d_in[2];
    const float* norm = (const float*)d_in[3];
    const int*   src  = (const int*)d_in[4];
    const int*   dst  = (const int*)d_in[5];
    const int*   rel  = (const int*)d_in[6];
    float* out = (float*)d_out;

    const int E  = in_sizes[4];
    const int EB = (E + 255) / 256;
    const dim3 pgrid(NBLK, NRELS);

    prep_w_kernel<<<(NRELS * FEAT * FEAT + 255) / 256, 256>>>(W);

    // pair compaction
    pair_init_kernel<<<(MAXPAIR + 255) / 256, 256>>>();
    pair_hist_kernel<<<EB, 256>>>(src, rel, E);
    pscan_block_kernel<<<pgrid, 256>>>();
    pscan_tops_kernel<<<NRELS, 512>>>();
    pad_base_kernel<<<1, 1>>>();
    pscan_add_kernel<<<pgrid, 256>>>();
    build_pairs_kernel<<<pgrid, 256>>>();

    // transform used pairs only (worst-case grid, device-side early exit)
    cudaFuncSetAttribute(transform_mma_kernel,
                         cudaFuncAttributeMaxDynamicSharedMemorySize, SM_TOTAL);
    transform_mma_kernel<<<MAXPAIR / 128, 256, SM_TOTAL>>>(h, gw);

    // dst sort
    zero_hist_kernel<<<NBLK, 256>>>();
    hist_kernel<<<EB, 256>>>(dst, E);
    scan_block_kernel<<<NBLK, 256>>>();
    scan_tops_kernel<<<1, 512>>>();
    scan_add_kernel<<<NBLK, 256>>>();
    scatter_kernel<<<EB, 256>>>(norm, src, dst, rel, E);

    // scatter-add + relu
    const int n4 = out_size / 4;
    zero_kernel<<<(n4 + 255) / 256, 256>>>((float4*)out, n4);
    const int warps = (E + CH - 1) / CH;
    edge_seg_kernel<<<(warps + 7) / 8, 256>>>(out, E);
    relu_kernel<<<(n4 + 255) / 256, 256>>>(out, n4);
}

// round 15
// speedup vs baseline: 2.2815x; 1.0805x over previous
#include <cuda_runtime.h>
#include <cuda_bf16.h>
#include <cuda_fp16.h>
#include <cstdint>
#include <cstddef>

#define FEAT  128
#define NRELS 8
#define MAXN  100000
#define MAXE  600000
#define KPAD  136           // padded k stride (elements): 272 B rows, conflict-free ldmatrix
#define NBINP 100096        // 391 * 256 >= MAXN (pair bins per rel, and dst bins)
#define NBLK  391
#define CH    16            // sorted edges per warp in segmented kernel
#define MAXPAIR (NRELS * NBINP)   // 800768: upper bound on padded compact pairs

// ---------------------------------------------------------------------------
// Global scratch (static __device__ arrays — sanctioned mechanism)
// ---------------------------------------------------------------------------
__device__ __half g_hall[(size_t)MAXPAIR * FEAT];                // [cid][F] fp16
__device__ unsigned short g_Bhi[NRELS * FEAT * KPAD];            // W^T hi bf16 padded
__device__ unsigned short g_Blo[NRELS * FEAT * KPAD];            // W^T lo
__device__ unsigned short g_Hhi[(size_t)MAXN * FEAT];            // h hi bf16 [node][128]
__device__ unsigned short g_Hlo[(size_t)MAXN * FEAT];            // h lo bf16
__device__ float          g_gate[(size_t)MAXN * NRELS];          // sigmoid(h.gw_r)
// pair compaction
__device__ unsigned int g_pflag[NRELS * NBINP];                  // usage count per (rel,src)
__device__ unsigned int g_pidx[NRELS * NBINP];                   // scan -> global compact id
__device__ unsigned int g_bsum2[NRELS * 512];
__device__ unsigned int g_boff2[NRELS * 512];
__device__ unsigned int g_ptot[NRELS];
__device__ unsigned int g_pbase[NRELS + 1];                      // padded rel bases; [8]=M
__device__ unsigned int g_pairsrc[MAXPAIR];                      // src per compact slot
// dst sort
__device__ unsigned int g_hist[NBINP];
__device__ unsigned int g_bsum[512];
__device__ unsigned int g_boff[512];
__device__ uint4        g_rec[MAXE];                             // sorted {cid, norm, dst, 0}

__device__ __forceinline__ uint32_t smem_to_u32(const void* p) {
    uint32_t a;
    asm("{ .reg .u64 t; cvta.to.shared.u64 t, %1; cvt.u32.u64 %0, t; }"
        : "=r"(a) : "l"(p));
    return a;
}

#define LDSM_X4(r0, r1, r2, r3, addr)                                          \
    asm volatile("ldmatrix.sync.aligned.m8n8.x4.shared.b16 {%0,%1,%2,%3}, [%4];" \
                 : "=r"(r0), "=r"(r1), "=r"(r2), "=r"(r3) : "r"(addr))

#define CP_ASYNC16(dst_u32, src_ptr)                                           \
    asm volatile("cp.async.ca.shared.global [%0], [%1], 16;"                   \
                 :: "r"(dst_u32), "l"(src_ptr))
#define CP_ASYNC_COMMIT() asm volatile("cp.async.commit_group;")
#define CP_ASYNC_WAIT()   asm volatile("cp.async.wait_group 0;" ::: "memory")

__device__ __forceinline__ void mma_bf16(float* c, uint32_t a0, uint32_t a1,
                                         uint32_t a2, uint32_t a3,
                                         uint32_t b0, uint32_t b1) {
    asm volatile(
        "mma.sync.aligned.m16n8k16.row.col.f32.bf16.bf16.f32 "
        "{%0,%1,%2,%3}, {%4,%5,%6,%7}, {%8,%9}, {%0,%1,%2,%3};"
        : "+f"(c[0]), "+f"(c[1]), "+f"(c[2]), "+f"(c[3])
        : "r"(a0), "r"(a1), "r"(a2), "r"(a3), "r"(b0), "r"(b1));
}

__device__ __forceinline__ uint32_t bf2_bits(__nv_bfloat162 v) {
    return *reinterpret_cast<uint32_t*>(&v);
}

// ---------------------------------------------------------------------------
// Prep W: W[r][k][f] -> W^T = B[n=f][k] hi/lo bf16, padded [r][128][KPAD].
// ---------------------------------------------------------------------------
__global__ void prep_w_kernel(const float* __restrict__ W) {
    const int idx = blockIdx.x * 256 + threadIdx.x;
    if (idx >= NRELS * FEAT * FEAT) return;
    const int r = idx >> 14;
    const int e = idx & 16383;
    const int n = e >> 7;
    const int k = e & 127;
    const float w = W[(size_t)r * FEAT * FEAT + k * FEAT + n];
    const __nv_bfloat16 hi = __float2bfloat16(w);
    const __nv_bfloat16 lo = __float2bfloat16(w - __bfloat162float(hi));
    const int o = (r * FEAT + n) * KPAD + k;
    g_Bhi[o] = *reinterpret_cast<const unsigned short*>(&hi);
    g_Blo[o] = *reinterpret_cast<const unsigned short*>(&lo);
}

// ---------------------------------------------------------------------------
// Split h once per node: g_Hhi/g_Hlo bf16, plus all 8 gates (warp per node).
// ---------------------------------------------------------------------------
__global__ __launch_bounds__(256)
void split_h_kernel(const float* __restrict__ h,
                    const float* __restrict__ gw, int N) {
    __shared__ float sgw[NRELS * FEAT];
    const int t = threadIdx.x;
    for (int i = t; i < NRELS * FEAT; i += 256) sgw[i] = gw[i];
    __syncthreads();

    const int node = blockIdx.x * 8 + (t >> 5);
    if (node >= N) return;
    const int lane = t & 31;

    const float4 v = __ldg((const float4*)(h + (size_t)node * FEAT) + lane);
    const float f[4] = {v.x, v.y, v.z, v.w};

    __nv_bfloat162 h01 = __floats2bfloat162_rn(f[0], f[1]);
    __nv_bfloat162 h23 = __floats2bfloat162_rn(f[2], f[3]);
    const float r0 = f[0] - __bfloat162float(__low2bfloat16(h01));
    const float r1 = f[1] - __bfloat162float(__high2bfloat16(h01));
    const float r2 = f[2] - __bfloat162float(__low2bfloat16(h23));
    const float r3 = f[3] - __bfloat162float(__high2bfloat16(h23));
    __nv_bfloat162 l01 = __floats2bfloat162_rn(r0, r1);
    __nv_bfloat162 l23 = __floats2bfloat162_rn(r2, r3);

    ((uint2*)(g_Hhi + (size_t)node * FEAT))[lane] =
        make_uint2(bf2_bits(h01), bf2_bits(h23));
    ((uint2*)(g_Hlo + (size_t)node * FEAT))[lane] =
        make_uint2(bf2_bits(l01), bf2_bits(l23));

    // gates: 8 warp-reduced dot products
#pragma unroll
    for (int r = 0; r < NRELS; r++) {
        const float* gwr = sgw + r * FEAT + lane * 4;
        float p = f[0] * gwr[0] + f[1] * gwr[1] + f[2] * gwr[2] + f[3] * gwr[3];
#pragma unroll
        for (int off = 16; off > 0; off >>= 1)
            p += __shfl_xor_sync(0xFFFFFFFFu, p, off);
        if (lane == 0)
            g_gate[(size_t)node * NRELS + r] = 1.f / (1.f + __expf(-p));
    }
}

// ---------------------------------------------------------------------------
// Pair compaction pipeline
// ---------------------------------------------------------------------------
__global__ void init_kernel() {
    const int i = blockIdx.x * 256 + threadIdx.x;
    if (i < NRELS * NBINP) g_pflag[i] = 0u;
    if (i < MAXPAIR)       g_pairsrc[i] = 0u;
    if (i < NBINP)         g_hist[i] = 0u;
}

__global__ void pair_hist_kernel(const int* __restrict__ src,
                                 const int* __restrict__ rel, int E) {
    const int e = blockIdx.x * 256 + threadIdx.x;
    if (e < E) atomicAdd(&g_pflag[rel[e] * NBINP + src[e]], 1u);
}

__global__ void pscan_block_kernel() {
    __shared__ unsigned int s[256];
    const int rel = blockIdx.y;
    const int t   = threadIdx.x;
    const int bin = rel * NBINP + blockIdx.x * 256 + t;
    const unsigned int v = g_pflag[bin] ? 1u : 0u;
    s[t] = v;
    __syncthreads();
#pragma unroll
    for (int off = 1; off < 256; off <<= 1) {
        unsigned int y = (t >= off) ? s[t - off] : 0u;
        __syncthreads();
        s[t] += y;
        __syncthreads();
    }
    g_pidx[bin] = s[t] - v;                       // exclusive within block
    if (t == 255) g_bsum2[rel * 512 + blockIdx.x] = s[255];
}

__global__ void pscan_tops_kernel() {
    __shared__ unsigned int s[512];
    const int rel = blockIdx.x;
    const int t   = threadIdx.x;
    const unsigned int v = (t < NBLK) ? g_bsum2[rel * 512 + t] : 0u;
    s[t] = v;
    __syncthreads();
#pragma unroll
    for (int off = 1; off < 512; off <<= 1) {
        unsigned int y = (t >= off) ? s[t - off] : 0u;
        __syncthreads();
        s[t] += y;
        __syncthreads();
    }
    if (t < NBLK) g_boff2[rel * 512 + t] = s[t] - v;
    if (t == NBLK - 1) g_ptot[rel] = s[t];
}

__global__ void pad_base_kernel() {
    unsigned int base = 0;
    for (int r = 0; r < NRELS; r++) {
        g_pbase[r] = base;
        base += ((g_ptot[r] + 127u) / 128u) * 128u;
    }
    g_pbase[NRELS] = base;
}

// folds the block-offset add into the build (one fewer 800k pass)
__global__ void build_pairs_kernel() {
    const int rel  = blockIdx.y;
    const int sidx = blockIdx.x * 256 + threadIdx.x;
    const int bin  = rel * NBINP + sidx;
    if (g_pflag[bin]) {
        const unsigned int cid = g_pbase[rel] + g_pidx[bin]
                               + g_boff2[rel * 512 + blockIdx.x];
        g_pairsrc[cid] = (unsigned int)sidx;
        g_pidx[bin]    = cid;
    }
}

// ---------------------------------------------------------------------------
// SMEM layout (bytes)
// ---------------------------------------------------------------------------
#define SM_GATE   0                        // 128 f32 = 512
#define SM_SRC    512                      // 128 u32 = 512
#define SM_AHI    1024                     // 128*KPAD bf16 = 34816
#define SM_ALO    35840
#define SM_BHI    70656
#define SM_BLO    105472
#define SM_TOTAL  140288                   // 137 KB

// ---------------------------------------------------------------------------
// Transform: one block per compact 128-pair tile (single relation each):
//   g_hall[cid,:] = fp16( (h[src] @ W_rel) * gate[src,rel] )
// Prologue is a pure cp.async gather of pre-split bf16 data.
// ---------------------------------------------------------------------------
__global__ __launch_bounds__(256, 1)
void transform_mma_kernel() {
    const int tile  = blockIdx.x;
    const int tbase = tile * 128;
    if ((unsigned)tbase >= g_pbase[NRELS]) return;

    int rel = 0;
#pragma unroll
    for (int r = 1; r < NRELS; r++)
        if ((unsigned)tbase >= g_pbase[r]) rel = r;

    extern __shared__ char smem[];
    const uint32_t sbase = smem_to_u32(smem);
    const int t    = threadIdx.x;
    const int wid  = t >> 5;
    const int lane = t & 31;

    // B panels via cp.async (linear copy, L2-resident)
    {
        const uint4* bh = (const uint4*)(g_Bhi + rel * FEAT * KPAD);
        const uint4* bl = (const uint4*)(g_Blo + rel * FEAT * KPAD);
        for (int i = t; i < FEAT * KPAD / 8; i += 256) {
            CP_ASYNC16(sbase + SM_BHI + i * 16, bh + i);
            CP_ASYNC16(sbase + SM_BLO + i * 16, bl + i);
        }
    }

    // A panels: gather pre-split rows by pairsrc via cp.async
    {
        const int row  = t & 127;
        const int half = t >> 7;
        const unsigned srcn = g_pairsrc[tbase + row];
        if (half == 0) ((unsigned*)(smem + SM_SRC))[row] = srcn;
        const char* ghi = (const char*)(g_Hhi + (size_t)srcn * FEAT) + half * 128;
        const char* glo = (const char*)(g_Hlo + (size_t)srcn * FEAT) + half * 128;
        const uint32_t d = (uint32_t)(row * (KPAD * 2) + half * 128);
#pragma unroll
        for (int c = 0; c < 8; c++) {
            CP_ASYNC16(sbase + SM_AHI + d + c * 16, ghi + c * 16);
            CP_ASYNC16(sbase + SM_ALO + d + c * 16, glo + c * 16);
        }
    }
    CP_ASYNC_COMMIT();
    CP_ASYNC_WAIT();
    __syncthreads();

    // gate lookup (precomputed sigmoid)
    if (t < FEAT) {
        const unsigned s = ((unsigned*)(smem + SM_SRC))[t];
        ((float*)(smem + SM_GATE))[t] = g_gate[(size_t)s * NRELS + rel];
    }
    __syncthreads();

    const int Moff = (wid & 3) * 32;
    const int Noff = (wid >> 2) * 64;
    const int q    = lane >> 3;
    const int lrow = lane & 7;
    const uint32_t a_off = (uint32_t)((Moff + (q & 1) * 8 + lrow) * (KPAD * 2)
                                      + (q >> 1) * 16);
    const uint32_t b_off = (uint32_t)((Noff + (q >> 1) * 8 + lrow) * (KPAD * 2)
                                      + (q & 1) * 16);

    float acc[2][8][4];
#pragma unroll
    for (int mt = 0; mt < 2; mt++)
#pragma unroll
        for (int nt = 0; nt < 8; nt++)
#pragma unroll
            for (int i = 0; i < 4; i++) acc[mt][nt][i] = 0.f;

#pragma unroll
    for (int ks = 0; ks < 8; ks++) {
        const uint32_t kb = (uint32_t)(ks * 32);
        uint32_t ah[2][4], al[2][4];
#pragma unroll
        for (int mt = 0; mt < 2; mt++) {
            const uint32_t mb = (uint32_t)(mt * 16 * KPAD * 2);
            LDSM_X4(ah[mt][0], ah[mt][1], ah[mt][2], ah[mt][3],
                    sbase + SM_AHI + mb + kb + a_off);
            LDSM_X4(al[mt][0], al[mt][1], al[mt][2], al[mt][3],
                    sbase + SM_ALO + mb + kb + a_off);
        }
        uint32_t bh[16], bl[16];
#pragma unroll
        for (int p = 0; p < 4; p++) {
            const uint32_t nb = (uint32_t)(p * 16 * KPAD * 2);
            LDSM_X4(bh[p * 4 + 0], bh[p * 4 + 1], bh[p * 4 + 2], bh[p * 4 + 3],
                    sbase + SM_BHI + nb + kb + b_off);
            LDSM_X4(bl[p * 4 + 0], bl[p * 4 + 1], bl[p * 4 + 2], bl[p * 4 + 3],
                    sbase + SM_BLO + nb + kb + b_off);
        }
#pragma unroll
        for (int mt = 0; mt < 2; mt++)
#pragma unroll
            for (int nt = 0; nt < 8; nt++) {
                const int bi = (nt >> 1) * 4 + (nt & 1) * 2;
                mma_bf16(acc[mt][nt], ah[mt][0], ah[mt][1], ah[mt][2], ah[mt][3],
                         bh[bi], bh[bi + 1]);
                mma_bf16(acc[mt][nt], ah[mt][0], ah[mt][1], ah[mt][2], ah[mt][3],
                         bl[bi], bl[bi + 1]);
                mma_bf16(acc[mt][nt], al[mt][0], al[mt][1], al[mt][2], al[mt][3],
                         bh[bi], bh[bi + 1]);
            }
    }

    // fp16 epilogue: scale by gate, store half2 to g_hall[cid]
    const float* gate = (const float*)(smem + SM_GATE);
    const int g  = lane >> 2;
    const int tq = lane & 3;
#pragma unroll
    for (int mt = 0; mt < 2; mt++) {
        const int row0 = Moff + mt * 16 + g;
        const int row1 = row0 + 8;
        const float s0 = gate[row0];
        const float s1 = gate[row1];
        __half* d0 = g_hall + (size_t)(tbase + row0) * FEAT;
        __half* d1 = g_hall + (size_t)(tbase + row1) * FEAT;
#pragma unroll
        for (int nt = 0; nt < 8; nt++) {
            const int col = Noff + nt * 8 + tq * 2;
            *(__half2*)(d0 + col) =
                __floats2half2_rn(acc[mt][nt][0] * s0, acc[mt][nt][1] * s0);
            *(__half2*)(d1 + col) =
                __floats2half2_rn(acc[mt][nt][2] * s1, acc[mt][nt][3] * s1);
        }
    }
}

// ---------------------------------------------------------------------------
// Counting sort by dst
// ---------------------------------------------------------------------------
__global__ void hist_kernel(const int* __restrict__ dst, int E) {
    const int e = blockIdx.x * 256 + threadIdx.x;
    if (e < E) atomicAdd(&g_hist[dst[e]], 1u);
}

__global__ void scan_block_kernel() {
    __shared__ unsigned int s[256];
    const int t   = threadIdx.x;
    const int bin = blockIdx.x * 256 + t;
    const unsigned int v = g_hist[bin];
    s[t] = v;
    __syncthreads();
#pragma unroll
    for (int off = 1; off < 256; off <<= 1) {
        unsigned int y = (t >= off) ? s[t - off] : 0u;
        __syncthreads();
        s[t] += y;
        __syncthreads();
    }
    g_hist[bin] = s[t] - v;
    if (t == 255) g_bsum[blockIdx.x] = s[255];
}

__global__ void scan_tops_kernel() {
    __shared__ unsigned int s[512];
    const int t = threadIdx.x;
    const unsigned int v = (t < NBLK) ? g_bsum[t] : 0u;
    s[t] = v;
    __syncthreads();
#pragma unroll
    for (int off = 1; off < 512; off <<= 1) {
        unsigned int y = (t >= off) ? s[t - off] : 0u;
        __syncthreads();
        s[t] += y;
        __syncthreads();
    }
    if (t < NBLK) g_boff[t] = s[t] - v;
}

__global__ void scan_add_kernel() {
    const int bin = blockIdx.x * 256 + threadIdx.x;
    g_hist[bin] += g_boff[blockIdx.x];
}

__global__ void scatter_kernel(const float* __restrict__ norm,
                               const int*   __restrict__ src,
                               const int*   __restrict__ dst,
                               const int*   __restrict__ rel,
                               int E) {
    const int e = blockIdx.x * 256 + threadIdx.x;
    if (e >= E) return;
    const int d = dst[e];
    const unsigned int pos = atomicAdd(&g_hist[d], 1u);
    const unsigned int cid = g_pidx[rel[e] * NBINP + src[e]];
    g_rec[pos] = make_uint4(cid, __float_as_uint(norm[e]), (unsigned)d, 0u);
}

// ---------------------------------------------------------------------------
// Segmented edge kernel: warp walks CH sorted edges, one red.v4 per dst run.
// ---------------------------------------------------------------------------
__global__ __launch_bounds__(256)
void edge_seg_kernel(float* __restrict__ out, int E) {
    const int warp = blockIdx.x * 8 + (threadIdx.x >> 5);
    const int lane = threadIdx.x & 31;
    const int base = warp * CH;
    if (base >= E) return;
    const int end = (base + CH < E) ? base + CH : E;

    float4 acc = make_float4(0.f, 0.f, 0.f, 0.f);
    int cur = -1;

    for (int e = base; e < end; e++) {
        const uint4 rec = __ldg(&g_rec[e]);
        const int d = (int)rec.z;
        if (d != cur) {
            if (cur >= 0) {
                float* o = out + (size_t)cur * FEAT + lane * 4;
                asm volatile("red.global.add.v4.f32 [%0], {%1, %2, %3, %4};"
                             :: "l"(o), "f"(acc.x), "f"(acc.y), "f"(acc.z), "f"(acc.w)
                             : "memory");
            }
            acc = make_float4(0.f, 0.f, 0.f, 0.f);
            cur = d;
        }
        const float nm = __uint_as_float(rec.y);
        const uint2 raw = __ldg((const uint2*)(g_hall + (size_t)rec.x * FEAT) + lane);
        const float2 f01 = __half22float2(*(const __half2*)&raw.x);
        const float2 f23 = __half22float2(*(const __half2*)&raw.y);
        acc.x = fmaf(f01.x, nm, acc.x);
        acc.y = fmaf(f01.y, nm, acc.y);
        acc.z = fmaf(f23.x, nm, acc.z);
        acc.w = fmaf(f23.y, nm, acc.w);
    }
    if (cur >= 0) {
        float* o = out + (size_t)cur * FEAT + lane * 4;
        asm volatile("red.global.add.v4.f32 [%0], {%1, %2, %3, %4};"
                     :: "l"(o), "f"(acc.x), "f"(acc.y), "f"(acc.z), "f"(acc.w)
                     : "memory");
    }
}

// ---------------------------------------------------------------------------
// Zero output / ReLU
// ---------------------------------------------------------------------------
__global__ void zero_kernel(float4* __restrict__ out, int n4) {
    const int i = blockIdx.x * blockDim.x + threadIdx.x;
    if (i < n4) out[i] = make_float4(0.f, 0.f, 0.f, 0.f);
}

__global__ void relu_kernel(float* __restrict__ out, int n4) {
    const int i = blockIdx.x * blockDim.x + threadIdx.x;
    if (i < n4) {
        float4 v = ((float4*)out)[i];
        v.x = fmaxf(v.x, 0.f);
        v.y = fmaxf(v.y, 0.f);
        v.z = fmaxf(v.z, 0.f);
        v.w = fmaxf(v.w, 0.f);
        ((float4*)out)[i] = v;
    }
}

// ---------------------------------------------------------------------------
// Launch
// ---------------------------------------------------------------------------
extern "C" void kernel_launch(void* const* d_in, const int* in_sizes, int n_in,
                              void* d_out, int out_size) {
    const float* h    = (const float*)d_in[0];
    const float* W    = (const float*)d_in[1];
    const float* gw   = (const float*)d_in[2];
    const float* norm = (const float*)d_in[3];
    const int*   src  = (const int*)d_in[4];
    const int*   dst  = (const int*)d_in[5];
    const int*   rel  = (const int*)d_in[6];
    float* out = (float*)d_out;

    const int N  = in_sizes[0] / FEAT;
    const int E  = in_sizes[4];
    const int EB = (E + 255) / 256;
    const dim3 pgrid(NBLK, NRELS);

    prep_w_kernel<<<(NRELS * FEAT * FEAT + 255) / 256, 256>>>(W);
    split_h_kernel<<<(N + 7) / 8, 256>>>(h, gw, N);

    // pair compaction
    init_kernel<<<(MAXPAIR + 255) / 256, 256>>>();
    pair_hist_kernel<<<EB, 256>>>(src, rel, E);
    pscan_block_kernel<<<pgrid, 256>>>();
    pscan_tops_kernel<<<NRELS, 512>>>();
    pad_base_kernel<<<1, 1>>>();
    build_pairs_kernel<<<pgrid, 256>>>();

    // transform used pairs only (worst-case grid, device-side early exit)
    cudaFuncSetAttribute(transform_mma_kernel,
                         cudaFuncAttributeMaxDynamicSharedMemorySize, SM_TOTAL);
    transform_mma_kernel<<<MAXPAIR / 128, 256, SM_TOTAL>>>();

    // dst sort
    hist_kernel<<<EB, 256>>>(dst, E);
    scan_block_kernel<<<NBLK, 256>>>();
    scan_tops_kernel<<<1, 512>>>();
    scan_add_kernel<<<NBLK, 256>>>();
    scatter_kernel<<<EB, 256>>>(norm, src, dst, rel, E);

    // scatter-add + relu
    const int n4 = out_size / 4;
    zero_kernel<<<(n4 + 255) / 256, 256>>>((float4*)out, n4);
    const int warps = (E + CH - 1) / CH;
    edge_seg_kernel<<<(warps + 7) / 8, 256>>>(out, E);
    relu_kernel<<<(n4 + 255) / 256, 256>>>(out, n4);
}

// round 16
// speedup vs baseline: 2.3097x; 1.0124x over previous
#include <cuda_runtime.h>
#include <cuda_bf16.h>
#include <cuda_fp16.h>
#include <cstdint>
#include <cstddef>

#define FEAT  128
#define NRELS 8
#define MAXN  100000
#define MAXE  600000
#define KPAD  136           // padded k stride (elements): 272 B rows, conflict-free ldmatrix
#define NBINP 100096        // 391 * 256 >= MAXN (pair bins per rel, and dst bins)
#define NBLK  391
#define CH    16            // sorted edges per warp in segmented kernel
#define MAXPAIR (NRELS * NBINP)   // 800768: upper bound on padded compact pairs

// ---------------------------------------------------------------------------
// Global scratch (static __device__ arrays — sanctioned mechanism)
// ---------------------------------------------------------------------------
__device__ __half g_hall[(size_t)MAXPAIR * FEAT];                // [cid][F] fp16
__device__ unsigned short g_Bhi[NRELS * FEAT * KPAD];            // W^T fp16 padded
__device__ unsigned short g_Hhi[(size_t)MAXN * FEAT];            // h hi fp16 [node][128]
__device__ unsigned short g_Hlo[(size_t)MAXN * FEAT];            // h lo fp16
__device__ float          g_gate[(size_t)MAXN * NRELS];          // sigmoid(h.gw_r)
// pair compaction
__device__ unsigned int g_pflag[NRELS * NBINP];                  // usage count per (rel,src)
__device__ unsigned int g_pidx[NRELS * NBINP];                   // scan -> global compact id
__device__ unsigned int g_bsum2[NRELS * 512];
__device__ unsigned int g_boff2[NRELS * 512];
__device__ unsigned int g_ptot[NRELS];
__device__ unsigned int g_pbase[NRELS + 1];                      // padded rel bases; [8]=M
__device__ unsigned int g_pairsrc[MAXPAIR];                      // src per compact slot
// dst sort
__device__ unsigned int g_hist[NBINP];
__device__ unsigned int g_bsum[512];
__device__ unsigned int g_boff[512];
__device__ uint4        g_rec[MAXE];                             // sorted {cid, norm, dst, 0}

__device__ __forceinline__ uint32_t smem_to_u32(const void* p) {
    uint32_t a;
    asm("{ .reg .u64 t; cvta.to.shared.u64 t, %1; cvt.u32.u64 %0, t; }"
        : "=r"(a) : "l"(p));
    return a;
}

#define LDSM_X4(r0, r1, r2, r3, addr)                                          \
    asm volatile("ldmatrix.sync.aligned.m8n8.x4.shared.b16 {%0,%1,%2,%3}, [%4];" \
                 : "=r"(r0), "=r"(r1), "=r"(r2), "=r"(r3) : "r"(addr))

#define CP_ASYNC16(dst_u32, src_ptr)                                           \
    asm volatile("cp.async.ca.shared.global [%0], [%1], 16;"                   \
                 :: "r"(dst_u32), "l"(src_ptr))
#define CP_ASYNC_COMMIT() asm volatile("cp.async.commit_group;")
#define CP_ASYNC_WAIT()   asm volatile("cp.async.wait_group 0;" ::: "memory")

// fp16 MMA m16n8k16, fp32 accumulate (arch-agnostic, sm_80+)
__device__ __forceinline__ void mma_fp16(float* c, uint32_t a0, uint32_t a1,
                                         uint32_t a2, uint32_t a3,
                                         uint32_t b0, uint32_t b1) {
    asm volatile(
        "mma.sync.aligned.m16n8k16.row.col.f32.f16.f16.f32 "
        "{%0,%1,%2,%3}, {%4,%5,%6,%7}, {%8,%9}, {%0,%1,%2,%3};"
        : "+f"(c[0]), "+f"(c[1]), "+f"(c[2]), "+f"(c[3])
        : "r"(a0), "r"(a1), "r"(a2), "r"(a3), "r"(b0), "r"(b1));
}

__device__ __forceinline__ uint32_t h2_bits(__half2 v) {
    return *reinterpret_cast<uint32_t*>(&v);
}

// ---------------------------------------------------------------------------
// Prep W: W[r][k][f] -> W^T = B[n=f][k] fp16, padded [r][128][KPAD].
// ---------------------------------------------------------------------------
__global__ void prep_w_kernel(const float* __restrict__ W) {
    const int idx = blockIdx.x * 256 + threadIdx.x;
    if (idx >= NRELS * FEAT * FEAT) return;
    const int r = idx >> 14;
    const int e = idx & 16383;
    const int n = e >> 7;
    const int k = e & 127;
    const float w = W[(size_t)r * FEAT * FEAT + k * FEAT + n];
    const __half hi = __float2half_rn(w);
    g_Bhi[(r * FEAT + n) * KPAD + k] = *reinterpret_cast<const unsigned short*>(&hi);
}

// ---------------------------------------------------------------------------
// Split h once per node to fp16 hi/lo, plus all 8 gates (warp per node).
// A = Ahi + Alo exact to ~2^-22; only B carries fp16 rounding error.
// ---------------------------------------------------------------------------
__global__ __launch_bounds__(256)
void split_h_kernel(const float* __restrict__ h,
                    const float* __restrict__ gw, int N) {
    __shared__ float sgw[NRELS * FEAT];
    const int t = threadIdx.x;
    for (int i = t; i < NRELS * FEAT; i += 256) sgw[i] = gw[i];
    __syncthreads();

    const int node = blockIdx.x * 8 + (t >> 5);
    if (node >= N) return;
    const int lane = t & 31;

    const float4 v = __ldg((const float4*)(h + (size_t)node * FEAT) + lane);
    const float f[4] = {v.x, v.y, v.z, v.w};

    const __half h0 = __float2half_rn(f[0]);
    const __half h1 = __float2half_rn(f[1]);
    const __half h2 = __float2half_rn(f[2]);
    const __half h3 = __float2half_rn(f[3]);
    const __half l0 = __float2half_rn(f[0] - __half2float(h0));
    const __half l1 = __float2half_rn(f[1] - __half2float(h1));
    const __half l2 = __float2half_rn(f[2] - __half2float(h2));
    const __half l3 = __float2half_rn(f[3] - __half2float(h3));

    ((uint2*)(g_Hhi + (size_t)node * FEAT))[lane] =
        make_uint2(h2_bits(__halves2half2(h0, h1)), h2_bits(__halves2half2(h2, h3)));
    ((uint2*)(g_Hlo + (size_t)node * FEAT))[lane] =
        make_uint2(h2_bits(__halves2half2(l0, l1)), h2_bits(__halves2half2(l2, l3)));

    // gates: 8 warp-reduced dot products (fp32)
#pragma unroll
    for (int r = 0; r < NRELS; r++) {
        const float* gwr = sgw + r * FEAT + lane * 4;
        float p = f[0] * gwr[0] + f[1] * gwr[1] + f[2] * gwr[2] + f[3] * gwr[3];
#pragma unroll
        for (int off = 16; off > 0; off >>= 1)
            p += __shfl_xor_sync(0xFFFFFFFFu, p, off);
        if (lane == 0)
            g_gate[(size_t)node * NRELS + r] = 1.f / (1.f + __expf(-p));
    }
}

// ---------------------------------------------------------------------------
// Pair compaction pipeline
// ---------------------------------------------------------------------------
__global__ void init_kernel() {
    const int i = blockIdx.x * 256 + threadIdx.x;
    if (i < NRELS * NBINP) g_pflag[i] = 0u;
    if (i < MAXPAIR)       g_pairsrc[i] = 0u;
    if (i < NBINP)         g_hist[i] = 0u;
}

__global__ void pair_hist_kernel(const int* __restrict__ src,
                                 const int* __restrict__ rel, int E) {
    const int e = blockIdx.x * 256 + threadIdx.x;
    if (e < E) atomicAdd(&g_pflag[rel[e] * NBINP + src[e]], 1u);
}

__global__ void pscan_block_kernel() {
    __shared__ unsigned int s[256];
    const int rel = blockIdx.y;
    const int t   = threadIdx.x;
    const int bin = rel * NBINP + blockIdx.x * 256 + t;
    const unsigned int v = g_pflag[bin] ? 1u : 0u;
    s[t] = v;
    __syncthreads();
#pragma unroll
    for (int off = 1; off < 256; off <<= 1) {
        unsigned int y = (t >= off) ? s[t - off] : 0u;
        __syncthreads();
        s[t] += y;
        __syncthreads();
    }
    g_pidx[bin] = s[t] - v;                       // exclusive within block
    if (t == 255) g_bsum2[rel * 512 + blockIdx.x] = s[255];
}

__global__ void pscan_tops_kernel() {
    __shared__ unsigned int s[512];
    const int rel = blockIdx.x;
    const int t   = threadIdx.x;
    const unsigned int v = (t < NBLK) ? g_bsum2[rel * 512 + t] : 0u;
    s[t] = v;
    __syncthreads();
#pragma unroll
    for (int off = 1; off < 512; off <<= 1) {
        unsigned int y = (t >= off) ? s[t - off] : 0u;
        __syncthreads();
        s[t] += y;
        __syncthreads();
    }
    if (t < NBLK) g_boff2[rel * 512 + t] = s[t] - v;
    if (t == NBLK - 1) g_ptot[rel] = s[t];
}

__global__ void pad_base_kernel() {
    unsigned int base = 0;
    for (int r = 0; r < NRELS; r++) {
        g_pbase[r] = base;
        base += ((g_ptot[r] + 127u) / 128u) * 128u;
    }
    g_pbase[NRELS] = base;
}

__global__ void build_pairs_kernel() {
    const int rel  = blockIdx.y;
    const int sidx = blockIdx.x * 256 + threadIdx.x;
    const int bin  = rel * NBINP + sidx;
    if (g_pflag[bin]) {
        const unsigned int cid = g_pbase[rel] + g_pidx[bin]
                               + g_boff2[rel * 512 + blockIdx.x];
        g_pairsrc[cid] = (unsigned int)sidx;
        g_pidx[bin]    = cid;
    }
}

// ---------------------------------------------------------------------------
// SMEM layout (bytes) — 103 KB => 2 blocks/SM
// ---------------------------------------------------------------------------
#define SM_GATE   0                        // 128 f32 = 512
#define SM_SRC    512                      // 128 u32 = 512
#define SM_AHI    1024                     // 128*KPAD fp16 = 34816
#define SM_ALO    35840
#define SM_BHI    70656
#define SM_TOTAL  105472                   // 103 KB

// ---------------------------------------------------------------------------
// Transform: one block per compact 128-pair tile (single relation each):
//   g_hall[cid,:] = fp16( (h[src] @ W_rel) * gate[src,rel] )
// 2-term fp16 split: Ahi*Bhi + Alo*Bhi (fp32 accum); 2 blocks/SM.
// ---------------------------------------------------------------------------
__global__ __launch_bounds__(256, 2)
void transform_mma_kernel() {
    const int tile  = blockIdx.x;
    const int tbase = tile * 128;
    if ((unsigned)tbase >= g_pbase[NRELS]) return;

    int rel = 0;
#pragma unroll
    for (int r = 1; r < NRELS; r++)
        if ((unsigned)tbase >= g_pbase[r]) rel = r;

    extern __shared__ char smem[];
    const uint32_t sbase = smem_to_u32(smem);
    const int t    = threadIdx.x;
    const int wid  = t >> 5;
    const int lane = t & 31;

    // B panel via cp.async (linear copy, L2-resident)
    {
        const uint4* bh = (const uint4*)(g_Bhi + rel * FEAT * KPAD);
        for (int i = t; i < FEAT * KPAD / 8; i += 256)
            CP_ASYNC16(sbase + SM_BHI + i * 16, bh + i);
    }

    // A panels: gather pre-split fp16 rows by pairsrc via cp.async
    {
        const int row  = t & 127;
        const int half = t >> 7;
        const unsigned srcn = g_pairsrc[tbase + row];
        if (half == 0) ((unsigned*)(smem + SM_SRC))[row] = srcn;
        const char* ghi = (const char*)(g_Hhi + (size_t)srcn * FEAT) + half * 128;
        const char* glo = (const char*)(g_Hlo + (size_t)srcn * FEAT) + half * 128;
        const uint32_t d = (uint32_t)(row * (KPAD * 2) + half * 128);
#pragma unroll
        for (int c = 0; c < 8; c++) {
            CP_ASYNC16(sbase + SM_AHI + d + c * 16, ghi + c * 16);
            CP_ASYNC16(sbase + SM_ALO + d + c * 16, glo + c * 16);
        }
    }
    CP_ASYNC_COMMIT();
    CP_ASYNC_WAIT();
    __syncthreads();

    // gate lookup (precomputed sigmoid)
    if (t < FEAT) {
        const unsigned s = ((unsigned*)(smem + SM_SRC))[t];
        ((float*)(smem + SM_GATE))[t] = g_gate[(size_t)s * NRELS + rel];
    }
    __syncthreads();

    const int Moff = (wid & 3) * 32;
    const int Noff = (wid >> 2) * 64;
    const int q    = lane >> 3;
    const int lrow = lane & 7;
    const uint32_t a_off = (uint32_t)((Moff + (q & 1) * 8 + lrow) * (KPAD * 2)
                                      + (q >> 1) * 16);
    const uint32_t b_off = (uint32_t)((Noff + (q >> 1) * 8 + lrow) * (KPAD * 2)
                                      + (q & 1) * 16);

    float acc[2][8][4];
#pragma unroll
    for (int mt = 0; mt < 2; mt++)
#pragma unroll
        for (int nt = 0; nt < 8; nt++)
#pragma unroll
            for (int i = 0; i < 4; i++) acc[mt][nt][i] = 0.f;

#pragma unroll
    for (int ks = 0; ks < 8; ks++) {
        const uint32_t kb = (uint32_t)(ks * 32);
        uint32_t ah[2][4], al[2][4];
#pragma unroll
        for (int mt = 0; mt < 2; mt++) {
            const uint32_t mb = (uint32_t)(mt * 16 * KPAD * 2);
            LDSM_X4(ah[mt][0], ah[mt][1], ah[mt][2], ah[mt][3],
                    sbase + SM_AHI + mb + kb + a_off);
            LDSM_X4(al[mt][0], al[mt][1], al[mt][2], al[mt][3],
                    sbase + SM_ALO + mb + kb + a_off);
        }
        uint32_t bh[16];
#pragma unroll
        for (int p = 0; p < 4; p++) {
            const uint32_t nb = (uint32_t)(p * 16 * KPAD * 2);
            LDSM_X4(bh[p * 4 + 0], bh[p * 4 + 1], bh[p * 4 + 2], bh[p * 4 + 3],
                    sbase + SM_BHI + nb + kb + b_off);
        }
#pragma unroll
        for (int mt = 0; mt < 2; mt++)
#pragma unroll
            for (int nt = 0; nt < 8; nt++) {
                const int bi = (nt >> 1) * 4 + (nt & 1) * 2;
                mma_fp16(acc[mt][nt], ah[mt][0], ah[mt][1], ah[mt][2], ah[mt][3],
                         bh[bi], bh[bi + 1]);
                mma_fp16(acc[mt][nt], al[mt][0], al[mt][1], al[mt][2], al[mt][3],
                         bh[bi], bh[bi + 1]);
            }
    }

    // fp16 epilogue: scale by gate, store half2 to g_hall[cid]
    const float* gate = (const float*)(smem + SM_GATE);
    const int g  = lane >> 2;
    const int tq = lane & 3;
#pragma unroll
    for (int mt = 0; mt < 2; mt++) {
        const int row0 = Moff + mt * 16 + g;
        const int row1 = row0 + 8;
        const float s0 = gate[row0];
        const float s1 = gate[row1];
        __half* d0 = g_hall + (size_t)(tbase + row0) * FEAT;
        __half* d1 = g_hall + (size_t)(tbase + row1) * FEAT;
#pragma unroll
        for (int nt = 0; nt < 8; nt++) {
            const int col = Noff + nt * 8 + tq * 2;
            *(__half2*)(d0 + col) =
                __floats2half2_rn(acc[mt][nt][0] * s0, acc[mt][nt][1] * s0);
            *(__half2*)(d1 + col) =
                __floats2half2_rn(acc[mt][nt][2] * s1, acc[mt][nt][3] * s1);
        }
    }
}

// ---------------------------------------------------------------------------
// Counting sort by dst
// ---------------------------------------------------------------------------
__global__ void hist_kernel(const int* __restrict__ dst, int E) {
    const int e = blockIdx.x * 256 + threadIdx.x;
    if (e < E) atomicAdd(&g_hist[dst[e]], 1u);
}

__global__ void scan_block_kernel() {
    __shared__ unsigned int s[256];
    const int t   = threadIdx.x;
    const int bin = blockIdx.x * 256 + t;
    const unsigned int v = g_hist[bin];
    s[t] = v;
    __syncthreads();
#pragma unroll
    for (int off = 1; off < 256; off <<= 1) {
        unsigned int y = (t >= off) ? s[t - off] : 0u;
        __syncthreads();
        s[t] += y;
        __syncthreads();
    }
    g_hist[bin] = s[t] - v;
    if (t == 255) g_bsum[blockIdx.x] = s[255];
}

__global__ void scan_tops_kernel() {
    __shared__ unsigned int s[512];
    const int t = threadIdx.x;
    const unsigned int v = (t < NBLK) ? g_bsum[t] : 0u;
    s[t] = v;
    __syncthreads();
#pragma unroll
    for (int off = 1; off < 512; off <<= 1) {
        unsigned int y = (t >= off) ? s[t - off] : 0u;
        __syncthreads();
        s[t] += y;
        __syncthreads();
    }
    if (t < NBLK) g_boff[t] = s[t] - v;
}

__global__ void scan_add_kernel() {
    const int bin = blockIdx.x * 256 + threadIdx.x;
    g_hist[bin] += g_boff[blockIdx.x];
}

__global__ void scatter_kernel(const float* __restrict__ norm,
                               const int*   __restrict__ src,
                               const int*   __restrict__ dst,
                               const int*   __restrict__ rel,
                               int E) {
    const int e = blockIdx.x * 256 + threadIdx.x;
    if (e >= E) return;
    const int d = dst[e];
    const unsigned int pos = atomicAdd(&g_hist[d], 1u);
    const unsigned int cid = g_pidx[rel[e] * NBINP + src[e]];
    g_rec[pos] = make_uint4(cid, __float_as_uint(norm[e]), (unsigned)d, 0u);
}

// ---------------------------------------------------------------------------
// Segmented edge kernel: warp walks CH sorted edges, one red.v4 per dst run.
// ---------------------------------------------------------------------------
__global__ __launch_bounds__(256)
void edge_seg_kernel(float* __restrict__ out, int E) {
    const int warp = blockIdx.x * 8 + (threadIdx.x >> 5);
    const int lane = threadIdx.x & 31;
    const int base = warp * CH;
    if (base >= E) return;
    const int end = (base + CH < E) ? base + CH : E;

    float4 acc = make_float4(0.f, 0.f, 0.f, 0.f);
    int cur = -1;

    for (int e = base; e < end; e++) {
        const uint4 rec = __ldg(&g_rec[e]);
        const int d = (int)rec.z;
        if (d != cur) {
            if (cur >= 0) {
                float* o = out + (size_t)cur * FEAT + lane * 4;
                asm volatile("red.global.add.v4.f32 [%0], {%1, %2, %3, %4};"
                             :: "l"(o), "f"(acc.x), "f"(acc.y), "f"(acc.z), "f"(acc.w)
                             : "memory");
            }
            acc = make_float4(0.f, 0.f, 0.f, 0.f);
            cur = d;
        }
        const float nm = __uint_as_float(rec.y);
        const uint2 raw = __ldg((const uint2*)(g_hall + (size_t)rec.x * FEAT) + lane);
        const float2 f01 = __half22float2(*(const __half2*)&raw.x);
        const float2 f23 = __half22float2(*(const __half2*)&raw.y);
        acc.x = fmaf(f01.x, nm, acc.x);
        acc.y = fmaf(f01.y, nm, acc.y);
        acc.z = fmaf(f23.x, nm, acc.z);
        acc.w = fmaf(f23.y, nm, acc.w);
    }
    if (cur >= 0) {
        float* o = out + (size_t)cur * FEAT + lane * 4;
        asm volatile("red.global.add.v4.f32 [%0], {%1, %2, %3, %4};"
                     :: "l"(o), "f"(acc.x), "f"(acc.y), "f"(acc.z), "f"(acc.w)
                     : "memory");
    }
}

// ---------------------------------------------------------------------------
// Zero output / ReLU
// ---------------------------------------------------------------------------
__global__ void zero_kernel(float4* __restrict__ out, int n4) {
    const int i = blockIdx.x * blockDim.x + threadIdx.x;
    if (i < n4) out[i] = make_float4(0.f, 0.f, 0.f, 0.f);
}

__global__ void relu_kernel(float* __restrict__ out, int n4) {
    const int i = blockIdx.x * blockDim.x + threadIdx.x;
    if (i < n4) {
        float4 v = ((float4*)out)[i];
        v.x = fmaxf(v.x, 0.f);
        v.y = fmaxf(v.y, 0.f);
        v.z = fmaxf(v.z, 0.f);
        v.w = fmaxf(v.w, 0.f);
        ((float4*)out)[i] = v;
    }
}

// ---------------------------------------------------------------------------
// Launch
// ---------------------------------------------------------------------------
extern "C" void kernel_launch(void* const* d_in, const int* in_sizes, int n_in,
                              void* d_out, int out_size) {
    const float* h    = (const float*)d_in[0];
    const float* W    = (const float*)d_in[1];
    const float* gw   = (const float*)d_in[2];
    const float* norm = (const float*)d_in[3];
    const int*   src  = (const int*)d_in[4];
    const int*   dst  = (const int*)d_in[5];
    const int*   rel  = (const int*)d_in[6];
    float* out = (float*)d_out;

    const int N  = in_sizes[0] / FEAT;
    const int E  = in_sizes[4];
    const int EB = (E + 255) / 256;
    const dim3 pgrid(NBLK, NRELS);

    prep_w_kernel<<<(NRELS * FEAT * FEAT + 255) / 256, 256>>>(W);
    split_h_kernel<<<(N + 7) / 8, 256>>>(h, gw, N);

    // pair compaction
    init_kernel<<<(MAXPAIR + 255) / 256, 256>>>();
    pair_hist_kernel<<<EB, 256>>>(src, rel, E);
    pscan_block_kernel<<<pgrid, 256>>>();
    pscan_tops_kernel<<<NRELS, 512>>>();
    pad_base_kernel<<<1, 1>>>();
    build_pairs_kernel<<<pgrid, 256>>>();

    // transform used pairs only (worst-case grid, device-side early exit)
    cudaFuncSetAttribute(transform_mma_kernel,
                         cudaFuncAttributeMaxDynamicSharedMemorySize, SM_TOTAL);
    transform_mma_kernel<<<MAXPAIR / 128, 256, SM_TOTAL>>>();

    // dst sort
    hist_kernel<<<EB, 256>>>(dst, E);
    scan_block_kernel<<<NBLK, 256>>>();
    scan_tops_kernel<<<1, 512>>>();
    scan_add_kernel<<<NBLK, 256>>>();
    scatter_kernel<<<EB, 256>>>(norm, src, dst, rel, E);

    // scatter-add + relu
    const int n4 = out_size / 4;
    zero_kernel<<<(n4 + 255) / 256, 256>>>((float4*)out, n4);
    const int warps = (E + CH - 1) / CH;
    edge_seg_kernel<<<(warps + 7) / 8, 256>>>(out, E);
    relu_kernel<<<(n4 + 255) / 256, 256>>>(out, n4);
}